// round 1
// baseline (speedup 1.0000x reference)
#include <cuda_runtime.h>
#include <math.h>

#define Bv   8
#define Tv   2048
#define Cv   1024
#define Hv   16
#define Nv   64
#define FFNv 3584
#define Mv   (Bv*Tv)          /* 16384 tokens */
#define EPSv 1e-5f

// ---------------------------------------------------------------------------
// Scratch pool (static device memory; no allocations anywhere).
// 16 buffers of [Mv*Cv] + one [Mv*FFNv]  = 327,155,712 floats (~1.31 GB)
// ---------------------------------------------------------------------------
#define MC   ((size_t)Mv * Cv)        /* 16,777,216 */
#define MF   ((size_t)Mv * FFNv)      /* 58,720,256 */
__device__ float g_pool[16 * MC + MF];

// pool offsets (in floats)
#define OFF_X0   (0*MC)
#define OFF_XN   (1*MC)
#define OFF_XR   (2*MC)
#define OFF_XK   (3*MC)
#define OFF_XV   (4*MC)
#define OFF_XG   (5*MC)
#define OFF_R    (6*MC)
#define OFF_K    (7*MC)
#define OFF_V    (8*MC)
#define OFF_G    (9*MC)
#define OFF_Y    (10*MC)
#define OFF_YM   (11*MC)
#define OFF_XN2  (12*MC)
#define OFF_XK2  (13*MC)
#define OFF_XR2  (14*MC)
#define OFF_SR   (15*MC)
#define OFF_KF   (16*MC)

// ---------------------------------------------------------------------------
// Block reduction helper (256 threads): sum + sumsq
// ---------------------------------------------------------------------------
__device__ __forceinline__ float2 block_reduce2(float s, float ss, float* shm /*16*/)
{
#pragma unroll
    for (int o = 16; o; o >>= 1) {
        s  += __shfl_xor_sync(0xffffffffu, s,  o);
        ss += __shfl_xor_sync(0xffffffffu, ss, o);
    }
    int w = threadIdx.x >> 5;
    if ((threadIdx.x & 31) == 0) { shm[w] = s; shm[8 + w] = ss; }
    __syncthreads();
    s = shm[0]; ss = shm[8];
#pragma unroll
    for (int i = 1; i < 8; i++) { s += shm[i]; ss += shm[8 + i]; }
    return make_float2(s, ss);
}

// ---------------------------------------------------------------------------
// LN0 + LN1 fused: x -> x0 = LN(x)*w0+b0 ; xn = LN(x0)*w1+b1
// one block per token, 256 threads, 4 floats/thread
// ---------------------------------------------------------------------------
__global__ __launch_bounds__(256) void ln01_kernel(
    const float* __restrict__ x,
    const float* __restrict__ w0, const float* __restrict__ b0,
    const float* __restrict__ w1, const float* __restrict__ b1,
    float* __restrict__ x0, float* __restrict__ xn)
{
    __shared__ float shm1[16], shm2[16];
    int m = blockIdx.x, tid = threadIdx.x;
    const float4 v = ((const float4*)(x + (size_t)m * Cv))[tid];

    float s  = v.x + v.y + v.z + v.w;
    float ss = v.x*v.x + v.y*v.y + v.z*v.z + v.w*v.w;
    float2 r = block_reduce2(s, ss, shm1);
    float mu  = r.x * (1.0f / Cv);
    float var = r.y * (1.0f / Cv) - mu * mu;
    float inv = rsqrtf(var + EPSv);

    const float4 wv0 = ((const float4*)w0)[tid];
    const float4 bv0 = ((const float4*)b0)[tid];
    float4 o;
    o.x = (v.x - mu) * inv * wv0.x + bv0.x;
    o.y = (v.y - mu) * inv * wv0.y + bv0.y;
    o.z = (v.z - mu) * inv * wv0.z + bv0.z;
    o.w = (v.w - mu) * inv * wv0.w + bv0.w;
    ((float4*)(x0 + (size_t)m * Cv))[tid] = o;

    s  = o.x + o.y + o.z + o.w;
    ss = o.x*o.x + o.y*o.y + o.z*o.z + o.w*o.w;
    r = block_reduce2(s, ss, shm2);
    mu  = r.x * (1.0f / Cv);
    var = r.y * (1.0f / Cv) - mu * mu;
    inv = rsqrtf(var + EPSv);

    const float4 wv1 = ((const float4*)w1)[tid];
    const float4 bv1 = ((const float4*)b1)[tid];
    float4 o2;
    o2.x = (o.x - mu) * inv * wv1.x + bv1.x;
    o2.y = (o.y - mu) * inv * wv1.y + bv1.y;
    o2.z = (o.z - mu) * inv * wv1.z + bv1.z;
    o2.w = (o.w - mu) * inv * wv1.w + bv1.w;
    ((float4*)(xn + (size_t)m * Cv))[tid] = o2;
}

// ---------------------------------------------------------------------------
// Plain LN: out = LN(in)*w + b
// ---------------------------------------------------------------------------
__global__ __launch_bounds__(256) void ln_kernel(
    const float* __restrict__ in,
    const float* __restrict__ w, const float* __restrict__ b,
    float* __restrict__ outp)
{
    __shared__ float shm[16];
    int m = blockIdx.x, tid = threadIdx.x;
    const float4 v = ((const float4*)(in + (size_t)m * Cv))[tid];
    float s  = v.x + v.y + v.z + v.w;
    float ss = v.x*v.x + v.y*v.y + v.z*v.z + v.w*v.w;
    float2 r = block_reduce2(s, ss, shm);
    float mu  = r.x * (1.0f / Cv);
    float var = r.y * (1.0f / Cv) - mu * mu;
    float inv = rsqrtf(var + EPSv);
    const float4 wv = ((const float4*)w)[tid];
    const float4 bv = ((const float4*)b)[tid];
    float4 o;
    o.x = (v.x - mu) * inv * wv.x + bv.x;
    o.y = (v.y - mu) * inv * wv.y + bv.y;
    o.z = (v.z - mu) * inv * wv.z + bv.z;
    o.w = (v.w - mu) * inv * wv.w + bv.w;
    ((float4*)(outp + (size_t)m * Cv))[tid] = o;
}

// ---------------------------------------------------------------------------
// token-shift mix producing 4 outputs (attention path)
// out = prev + (cur - prev) * tm
// ---------------------------------------------------------------------------
__global__ __launch_bounds__(256) void mix4_kernel(
    const float* __restrict__ xn,
    const float* __restrict__ tmk, const float* __restrict__ tmv,
    const float* __restrict__ tmr, const float* __restrict__ tmg,
    float* __restrict__ xk, float* __restrict__ xv,
    float* __restrict__ xr, float* __restrict__ xg)
{
    const int C4 = Cv / 4;
    int idx = blockIdx.x * blockDim.x + threadIdx.x;    // float4 index
    int m  = idx / C4;
    int c4 = idx - m * C4;
    float4 a = ((const float4*)xn)[idx];
    float4 p = make_float4(0.f, 0.f, 0.f, 0.f);
    if ((m % Tv) != 0) p = ((const float4*)xn)[idx - C4];
    float4 d = make_float4(a.x - p.x, a.y - p.y, a.z - p.z, a.w - p.w);

#define DO_MIX(TM, OUT) { \
    float4 w = ((const float4*)TM)[c4]; \
    float4 o; \
    o.x = fmaf(d.x, w.x, p.x); o.y = fmaf(d.y, w.y, p.y); \
    o.z = fmaf(d.z, w.z, p.z); o.w = fmaf(d.w, w.w, p.w); \
    ((float4*)OUT)[idx] = o; }

    DO_MIX(tmk, xk)
    DO_MIX(tmv, xv)
    DO_MIX(tmr, xr)
    DO_MIX(tmg, xg)
#undef DO_MIX
}

// two-output variant (ffn path)
__global__ __launch_bounds__(256) void mix2_kernel(
    const float* __restrict__ xn,
    const float* __restrict__ tmk, const float* __restrict__ tmr,
    float* __restrict__ xk, float* __restrict__ xr)
{
    const int C4 = Cv / 4;
    int idx = blockIdx.x * blockDim.x + threadIdx.x;
    int m  = idx / C4;
    int c4 = idx - m * C4;
    float4 a = ((const float4*)xn)[idx];
    float4 p = make_float4(0.f, 0.f, 0.f, 0.f);
    if ((m % Tv) != 0) p = ((const float4*)xn)[idx - C4];
    float4 d = make_float4(a.x - p.x, a.y - p.y, a.z - p.z, a.w - p.w);
#define DO_MIX(TM, OUT) { \
    float4 w = ((const float4*)TM)[c4]; \
    float4 o; \
    o.x = fmaf(d.x, w.x, p.x); o.y = fmaf(d.y, w.y, p.y); \
    o.z = fmaf(d.z, w.z, p.z); o.w = fmaf(d.w, w.w, p.w); \
    ((float4*)OUT)[idx] = o; }
    DO_MIX(tmk, xk)
    DO_MIX(tmr, xr)
#undef DO_MIX
}

// ---------------------------------------------------------------------------
// NT GEMM: C[M,N] = A[M,K] @ B[N,K]^T, fp32, 128x128x16 tile, 8x8 microtile.
// Epilogues: 0 none, 1 silu, 2 relu^2, 3 sigmoid, 4 +res, 5 C += mul*acc
// ---------------------------------------------------------------------------
template<int EP>
__global__ __launch_bounds__(256) void gemm_nt(
    const float* __restrict__ A, const float* __restrict__ B,
    float* __restrict__ C, int M, int N, int K,
    const float* __restrict__ res, const float* __restrict__ mul)
{
    const int BM = 128, BN = 128, BK = 16;
    __shared__ float As[BK][BM + 4];
    __shared__ float Bs[BK][BN + 4];

    int bm = blockIdx.y * BM, bn = blockIdx.x * BN;
    int tid = threadIdx.x;
    int tm = (tid / 16) * 8;
    int tn = (tid % 16) * 8;

    int lr = tid >> 2;          // 0..63
    int lc = (tid & 3) * 4;     // 0,4,8,12

    const float* Ap = A + (size_t)(bm + lr) * K + lc;
    const float* Bp = B + (size_t)(bn + lr) * K + lc;

    float acc[8][8];
#pragma unroll
    for (int i = 0; i < 8; i++)
#pragma unroll
        for (int j = 0; j < 8; j++) acc[i][j] = 0.f;

    for (int k0 = 0; k0 < K; k0 += BK) {
        float4 a0 = *(const float4*)(Ap + k0);
        float4 a1 = *(const float4*)(Ap + (size_t)64 * K + k0);
        float4 b0 = *(const float4*)(Bp + k0);
        float4 b1 = *(const float4*)(Bp + (size_t)64 * K + k0);
        __syncthreads();
        As[lc + 0][lr] = a0.x; As[lc + 1][lr] = a0.y;
        As[lc + 2][lr] = a0.z; As[lc + 3][lr] = a0.w;
        As[lc + 0][lr + 64] = a1.x; As[lc + 1][lr + 64] = a1.y;
        As[lc + 2][lr + 64] = a1.z; As[lc + 3][lr + 64] = a1.w;
        Bs[lc + 0][lr] = b0.x; Bs[lc + 1][lr] = b0.y;
        Bs[lc + 2][lr] = b0.z; Bs[lc + 3][lr] = b0.w;
        Bs[lc + 0][lr + 64] = b1.x; Bs[lc + 1][lr + 64] = b1.y;
        Bs[lc + 2][lr + 64] = b1.z; Bs[lc + 3][lr + 64] = b1.w;
        __syncthreads();

#pragma unroll
        for (int kk = 0; kk < BK; kk++) {
            float ar[8], br[8];
            *(float4*)(ar)     = *(const float4*)&As[kk][tm];
            *(float4*)(ar + 4) = *(const float4*)&As[kk][tm + 4];
            *(float4*)(br)     = *(const float4*)&Bs[kk][tn];
            *(float4*)(br + 4) = *(const float4*)&Bs[kk][tn + 4];
#pragma unroll
            for (int i = 0; i < 8; i++)
#pragma unroll
                for (int j = 0; j < 8; j++)
                    acc[i][j] = fmaf(ar[i], br[j], acc[i][j]);
        }
    }

#pragma unroll
    for (int i = 0; i < 8; i++) {
        size_t row = (size_t)(bm + tm + i);
#pragma unroll
        for (int j = 0; j < 8; j++) {
            size_t idx = row * N + (bn + tn + j);
            float a = acc[i][j];
            float o;
            if (EP == 0)      o = a;
            else if (EP == 1) o = a / (1.f + expf(-a));          // silu
            else if (EP == 2) { float z = fmaxf(a, 0.f); o = z * z; }
            else if (EP == 3) o = 1.f / (1.f + expf(-a));        // sigmoid
            else if (EP == 4) o = a + res[idx];                  // + residual
            else              o = C[idx] + mul[idx] * a;         // C += mul*acc
            C[idx] = o;
        }
    }
}

// ---------------------------------------------------------------------------
// WKV5 recurrence. One block per (b,h). 256 threads: j = tid>>2 (output col),
// gq = tid&3 selects 16-row i-slab. State column S[i,j] lives in registers.
// r/k/v staged through SMEM in 8-step chunks.
// ---------------------------------------------------------------------------
__global__ __launch_bounds__(256) void wkv_kernel(
    const float* __restrict__ r, const float* __restrict__ k,
    const float* __restrict__ v,
    const float* __restrict__ decay, const float* __restrict__ faaaa,
    float* __restrict__ y)
{
    const int CH = 8;
    __shared__ float sr[CH][Nv], sk[CH][Nv], sv[CH][Nv];

    int bh = blockIdx.x;
    int b = bh / Hv, h = bh % Hv;
    int tid = threadIdx.x;
    int j  = tid >> 2;
    int gq = tid & 3;
    int ib = gq * 16;

    float S[16], ew[16], uu[16];
#pragma unroll
    for (int ii = 0; ii < 16; ii++) {
        S[ii]  = 0.f;
        ew[ii] = expf(-expf(decay[h * Nv + ib + ii]));
        uu[ii] = faaaa[h * Nv + ib + ii];
    }

    size_t base = ((size_t)b * Tv) * Cv + (size_t)h * Nv;

    for (int tc = 0; tc < Tv; tc += CH) {
        __syncthreads();
        for (int idx = tid; idx < CH * Nv; idx += 256) {
            int st = idx >> 6, c = idx & 63;
            size_t off = base + (size_t)(tc + st) * Cv + c;
            sr[st][c] = r[off];
            sk[st][c] = k[off];
            sv[st][c] = v[off];
        }
        __syncthreads();

#pragma unroll
        for (int st = 0; st < CH; st++) {
            float vj = sv[st][j];
            float y0 = 0.f;
#pragma unroll
            for (int ii = 0; ii < 16; ii++) {
                float ri = sr[st][ib + ii];
                float ki = sk[st][ib + ii];
                float t = ki * vj;
                y0 = fmaf(ri, fmaf(uu[ii], t, S[ii]), y0);
                S[ii] = fmaf(ew[ii], S[ii], t);
            }
            y0 += __shfl_xor_sync(0xffffffffu, y0, 1);
            y0 += __shfl_xor_sync(0xffffffffu, y0, 2);
            if (gq == 0)
                y[base + (size_t)(tc + st) * Cv + j] = y0;
        }
    }
}

// ---------------------------------------------------------------------------
// y/8 -> per-head GroupNorm -> *lnx_w + lnx_b -> * g(silu already applied)
// block per token, 256 threads, 4 floats/thread; 16 lanes == 1 head
// ---------------------------------------------------------------------------
__global__ __launch_bounds__(256) void gnmul_kernel(
    const float* __restrict__ y, const float* __restrict__ g,
    const float* __restrict__ w, const float* __restrict__ b,
    float* __restrict__ ym)
{
    int m = blockIdx.x, tid = threadIdx.x;
    size_t base = (size_t)m * Cv;
    float4 v = ((const float4*)(y + base))[tid];
    const float s8 = 1.0f / 8.0f;
    v.x *= s8; v.y *= s8; v.z *= s8; v.w *= s8;

    float s  = v.x + v.y + v.z + v.w;
    float ss = v.x*v.x + v.y*v.y + v.z*v.z + v.w*v.w;
#pragma unroll
    for (int o = 8; o; o >>= 1) {
        s  += __shfl_xor_sync(0xffffffffu, s,  o);
        ss += __shfl_xor_sync(0xffffffffu, ss, o);
    }
    float mu  = s * (1.0f / Nv);
    float var = ss * (1.0f / Nv) - mu * mu;
    float inv = rsqrtf(var + EPSv);

    float4 wv = ((const float4*)w)[tid];
    float4 bv = ((const float4*)b)[tid];
    float4 gv = ((const float4*)(g + base))[tid];
    float4 o;
    o.x = ((v.x - mu) * inv * wv.x + bv.x) * gv.x;
    o.y = ((v.y - mu) * inv * wv.y + bv.y) * gv.y;
    o.z = ((v.z - mu) * inv * wv.z + bv.z) * gv.z;
    o.w = ((v.w - mu) * inv * wv.w + bv.w) * gv.w;
    ((float4*)(ym + base))[tid] = o;
}

// ---------------------------------------------------------------------------
// launch
// ---------------------------------------------------------------------------
extern "C" void kernel_launch(void* const* d_in, const int* in_sizes, int n_in,
                              void* d_out, int out_size)
{
    const float* x        = (const float*)d_in[0];
    const float* ln0_w    = (const float*)d_in[1];
    const float* ln0_b    = (const float*)d_in[2];
    const float* ln1_w    = (const float*)d_in[3];
    const float* ln1_b    = (const float*)d_in[4];
    const float* ln2_w    = (const float*)d_in[5];
    const float* ln2_b    = (const float*)d_in[6];
    const float* att_tmk  = (const float*)d_in[7];
    const float* att_tmv  = (const float*)d_in[8];
    const float* att_tmr  = (const float*)d_in[9];
    const float* att_tmg  = (const float*)d_in[10];
    const float* att_decay  = (const float*)d_in[11];
    const float* att_faaaa  = (const float*)d_in[12];
    const float* att_Wr   = (const float*)d_in[13];
    const float* att_Wk   = (const float*)d_in[14];
    const float* att_Wv   = (const float*)d_in[15];
    const float* att_Wg   = (const float*)d_in[16];
    const float* att_Wo   = (const float*)d_in[17];
    const float* att_lnx_w = (const float*)d_in[18];
    const float* att_lnx_b = (const float*)d_in[19];
    const float* ffn_tmk  = (const float*)d_in[20];
    const float* ffn_tmr  = (const float*)d_in[21];
    const float* ffn_Wk   = (const float*)d_in[22];
    const float* ffn_Wr   = (const float*)d_in[23];
    const float* ffn_Wv   = (const float*)d_in[24];
    float* out = (float*)d_out;

    void* poolv = nullptr;
    cudaGetSymbolAddress(&poolv, g_pool);
    float* pool = (float*)poolv;

    float* bx0  = pool + OFF_X0;
    float* bxn  = pool + OFF_XN;
    float* bxr  = pool + OFF_XR;
    float* bxk  = pool + OFF_XK;
    float* bxv  = pool + OFF_XV;
    float* bxg  = pool + OFF_XG;
    float* br   = pool + OFF_R;
    float* bk   = pool + OFF_K;
    float* bv   = pool + OFF_V;
    float* bg   = pool + OFF_G;
    float* by   = pool + OFF_Y;
    float* bym  = pool + OFF_YM;
    float* bxn2 = pool + OFF_XN2;
    float* bxk2 = pool + OFF_XK2;
    float* bxr2 = pool + OFF_XR2;
    float* bsr  = pool + OFF_SR;
    float* bkf  = pool + OFF_KF;

    const int mixBlocks = (Mv * (Cv / 4)) / 256;      // 16384
    dim3 gC(Cv / 128, Mv / 128);                      // (8,128)
    dim3 gF(FFNv / 128, Mv / 128);                    // (28,128)

    // attention path
    ln01_kernel<<<Mv, 256>>>(x, ln0_w, ln0_b, ln1_w, ln1_b, bx0, bxn);
    mix4_kernel<<<mixBlocks, 256>>>(bxn, att_tmk, att_tmv, att_tmr, att_tmg,
                                    bxk, bxv, bxr, bxg);
    gemm_nt<0><<<gC, 256>>>(bxr, att_Wr, br, Mv, Cv, Cv, nullptr, nullptr);
    gemm_nt<0><<<gC, 256>>>(bxk, att_Wk, bk, Mv, Cv, Cv, nullptr, nullptr);
    gemm_nt<0><<<gC, 256>>>(bxv, att_Wv, bv, Mv, Cv, Cv, nullptr, nullptr);
    gemm_nt<1><<<gC, 256>>>(bxg, att_Wg, bg, Mv, Cv, Cv, nullptr, nullptr);  // silu
    wkv_kernel<<<Bv * Hv, 256>>>(br, bk, bv, att_decay, att_faaaa, by);
    gnmul_kernel<<<Mv, 256>>>(by, bg, att_lnx_w, att_lnx_b, bym);
    gemm_nt<4><<<gC, 256>>>(bym, att_Wo, out, Mv, Cv, Cv, bx0, nullptr);    // +x0

    // channel-mix path
    ln_kernel<<<Mv, 256>>>(out, ln2_w, ln2_b, bxn2);
    mix2_kernel<<<mixBlocks, 256>>>(bxn2, ffn_tmk, ffn_tmr, bxk2, bxr2);
    gemm_nt<2><<<gF, 256>>>(bxk2, ffn_Wk, bkf, Mv, FFNv, Cv, nullptr, nullptr); // relu^2
    gemm_nt<3><<<gC, 256>>>(bxr2, ffn_Wr, bsr, Mv, Cv, Cv, nullptr, nullptr);   // sigmoid
    gemm_nt<5><<<gC, 256>>>(bkf, ffn_Wv, out, Mv, Cv, FFNv, nullptr, bsr);      // out += sr*kv
}

// round 2
// speedup vs baseline: 1.9723x; 1.9723x over previous
#include <cuda_runtime.h>
#include <cstdint>
#include <math.h>

#define Bv   8
#define Tv   2048
#define Cv   1024
#define Hv   16
#define Nv   64
#define FFNv 3584
#define Mv   (Bv*Tv)          /* 16384 tokens */
#define EPSv 1e-5f

// ---------------------------------------------------------------------------
// Scratch pool (static device memory; no allocations anywhere).
// ---------------------------------------------------------------------------
#define MC   ((size_t)Mv * Cv)        /* 16,777,216 */
#define MF   ((size_t)Mv * FFNv)      /* 58,720,256 */
__device__ float g_pool[16 * MC + MF];

#define OFF_X0   (0*MC)
#define OFF_XN   (1*MC)
#define OFF_XR   (2*MC)
#define OFF_XK   (3*MC)
#define OFF_XV   (4*MC)
#define OFF_XG   (5*MC)
#define OFF_R    (6*MC)
#define OFF_K    (7*MC)
#define OFF_V    (8*MC)
#define OFF_G    (9*MC)
#define OFF_Y    (10*MC)
#define OFF_YM   (11*MC)
#define OFF_XN2  (12*MC)
#define OFF_XK2  (13*MC)
#define OFF_XR2  (14*MC)
#define OFF_SR   (15*MC)
#define OFF_KF   (16*MC)

// ---------------------------------------------------------------------------
// helpers
// ---------------------------------------------------------------------------
__device__ __forceinline__ float2 block_reduce2(float s, float ss, float* shm /*16*/)
{
#pragma unroll
    for (int o = 16; o; o >>= 1) {
        s  += __shfl_xor_sync(0xffffffffu, s,  o);
        ss += __shfl_xor_sync(0xffffffffu, ss, o);
    }
    int w = threadIdx.x >> 5;
    if ((threadIdx.x & 31) == 0) { shm[w] = s; shm[8 + w] = ss; }
    __syncthreads();
    s = shm[0]; ss = shm[8];
#pragma unroll
    for (int i = 1; i < 8; i++) { s += shm[i]; ss += shm[8 + i]; }
    return make_float2(s, ss);
}

__device__ __forceinline__ uint32_t f2tf32(float x)
{
    asm("cvt.rna.tf32.f32 %0, %0;" : "+f"(x));
    return __float_as_uint(x);
}

__device__ __forceinline__ void cp_async16(void* smem, const void* gptr)
{
    unsigned saddr = (unsigned)__cvta_generic_to_shared(smem);
    asm volatile("cp.async.ca.shared.global [%0], [%1], 16;\n" :: "r"(saddr), "l"(gptr));
}
#define CP_COMMIT() asm volatile("cp.async.commit_group;\n" ::: "memory")
#define CP_WAIT0()  asm volatile("cp.async.wait_group 0;\n" ::: "memory")

// ---------------------------------------------------------------------------
// LN0 + LN1 fused
// ---------------------------------------------------------------------------
__global__ __launch_bounds__(256) void ln01_kernel(
    const float* __restrict__ x,
    const float* __restrict__ w0, const float* __restrict__ b0,
    const float* __restrict__ w1, const float* __restrict__ b1,
    float* __restrict__ x0, float* __restrict__ xn)
{
    __shared__ float shm1[16], shm2[16];
    int m = blockIdx.x, tid = threadIdx.x;
    const float4 v = ((const float4*)(x + (size_t)m * Cv))[tid];

    float s  = v.x + v.y + v.z + v.w;
    float ss = v.x*v.x + v.y*v.y + v.z*v.z + v.w*v.w;
    float2 r = block_reduce2(s, ss, shm1);
    float mu  = r.x * (1.0f / Cv);
    float var = r.y * (1.0f / Cv) - mu * mu;
    float inv = rsqrtf(var + EPSv);

    const float4 wv0 = ((const float4*)w0)[tid];
    const float4 bv0 = ((const float4*)b0)[tid];
    float4 o;
    o.x = (v.x - mu) * inv * wv0.x + bv0.x;
    o.y = (v.y - mu) * inv * wv0.y + bv0.y;
    o.z = (v.z - mu) * inv * wv0.z + bv0.z;
    o.w = (v.w - mu) * inv * wv0.w + bv0.w;
    ((float4*)(x0 + (size_t)m * Cv))[tid] = o;

    s  = o.x + o.y + o.z + o.w;
    ss = o.x*o.x + o.y*o.y + o.z*o.z + o.w*o.w;
    r = block_reduce2(s, ss, shm2);
    mu  = r.x * (1.0f / Cv);
    var = r.y * (1.0f / Cv) - mu * mu;
    inv = rsqrtf(var + EPSv);

    const float4 wv1 = ((const float4*)w1)[tid];
    const float4 bv1 = ((const float4*)b1)[tid];
    float4 o2;
    o2.x = (o.x - mu) * inv * wv1.x + bv1.x;
    o2.y = (o.y - mu) * inv * wv1.y + bv1.y;
    o2.z = (o.z - mu) * inv * wv1.z + bv1.z;
    o2.w = (o.w - mu) * inv * wv1.w + bv1.w;
    ((float4*)(xn + (size_t)m * Cv))[tid] = o2;
}

__global__ __launch_bounds__(256) void ln_kernel(
    const float* __restrict__ in,
    const float* __restrict__ w, const float* __restrict__ b,
    float* __restrict__ outp)
{
    __shared__ float shm[16];
    int m = blockIdx.x, tid = threadIdx.x;
    const float4 v = ((const float4*)(in + (size_t)m * Cv))[tid];
    float s  = v.x + v.y + v.z + v.w;
    float ss = v.x*v.x + v.y*v.y + v.z*v.z + v.w*v.w;
    float2 r = block_reduce2(s, ss, shm);
    float mu  = r.x * (1.0f / Cv);
    float var = r.y * (1.0f / Cv) - mu * mu;
    float inv = rsqrtf(var + EPSv);
    const float4 wv = ((const float4*)w)[tid];
    const float4 bv = ((const float4*)b)[tid];
    float4 o;
    o.x = (v.x - mu) * inv * wv.x + bv.x;
    o.y = (v.y - mu) * inv * wv.y + bv.y;
    o.z = (v.z - mu) * inv * wv.z + bv.z;
    o.w = (v.w - mu) * inv * wv.w + bv.w;
    ((float4*)(outp + (size_t)m * Cv))[tid] = o;
}

// ---------------------------------------------------------------------------
// token-shift mix
// ---------------------------------------------------------------------------
__global__ __launch_bounds__(256) void mix4_kernel(
    const float* __restrict__ xn,
    const float* __restrict__ tmk, const float* __restrict__ tmv,
    const float* __restrict__ tmr, const float* __restrict__ tmg,
    float* __restrict__ xk, float* __restrict__ xv,
    float* __restrict__ xr, float* __restrict__ xg)
{
    const int C4 = Cv / 4;
    int idx = blockIdx.x * blockDim.x + threadIdx.x;
    int m  = idx / C4;
    int c4 = idx - m * C4;
    float4 a = ((const float4*)xn)[idx];
    float4 p = make_float4(0.f, 0.f, 0.f, 0.f);
    if ((m % Tv) != 0) p = ((const float4*)xn)[idx - C4];
    float4 d = make_float4(a.x - p.x, a.y - p.y, a.z - p.z, a.w - p.w);

#define DO_MIX(TM, OUT) { \
    float4 w = ((const float4*)TM)[c4]; \
    float4 o; \
    o.x = fmaf(d.x, w.x, p.x); o.y = fmaf(d.y, w.y, p.y); \
    o.z = fmaf(d.z, w.z, p.z); o.w = fmaf(d.w, w.w, p.w); \
    ((float4*)OUT)[idx] = o; }

    DO_MIX(tmk, xk)
    DO_MIX(tmv, xv)
    DO_MIX(tmr, xr)
    DO_MIX(tmg, xg)
#undef DO_MIX
}

__global__ __launch_bounds__(256) void mix2_kernel(
    const float* __restrict__ xn,
    const float* __restrict__ tmk, const float* __restrict__ tmr,
    float* __restrict__ xk, float* __restrict__ xr)
{
    const int C4 = Cv / 4;
    int idx = blockIdx.x * blockDim.x + threadIdx.x;
    int m  = idx / C4;
    int c4 = idx - m * C4;
    float4 a = ((const float4*)xn)[idx];
    float4 p = make_float4(0.f, 0.f, 0.f, 0.f);
    if ((m % Tv) != 0) p = ((const float4*)xn)[idx - C4];
    float4 d = make_float4(a.x - p.x, a.y - p.y, a.z - p.z, a.w - p.w);
#define DO_MIX(TM, OUT) { \
    float4 w = ((const float4*)TM)[c4]; \
    float4 o; \
    o.x = fmaf(d.x, w.x, p.x); o.y = fmaf(d.y, w.y, p.y); \
    o.z = fmaf(d.z, w.z, p.z); o.w = fmaf(d.w, w.w, p.w); \
    ((float4*)OUT)[idx] = o; }
    DO_MIX(tmk, xk)
    DO_MIX(tmr, xr)
#undef DO_MIX
}

// ---------------------------------------------------------------------------
// TF32 tensor-core NT GEMM: C[M,N] = A[M,K] @ B[N,K]^T
// 128x128x16 CTA tile, 8 warps of 32x64 (2x8 m16n8k8 tiles), cp.async
// double buffer. Smem [row][20] padding -> conflict-free fragment loads.
// Epilogues: 0 none, 1 silu, 2 relu^2, 3 sigmoid, 4 +res, 5 C += mul*acc
// ---------------------------------------------------------------------------
template<int EP>
__global__ __launch_bounds__(256) void gemm_tf32(
    const float* __restrict__ A, const float* __restrict__ B,
    float* __restrict__ C, int M, int N, int K,
    const float* __restrict__ res, const float* __restrict__ mul)
{
    const int BM = 128, BN = 128, BK = 16;
    __shared__ float As[2][BM][20];
    __shared__ float Bs[2][BN][20];

    const int tid  = threadIdx.x;
    const int wid  = tid >> 5;
    const int lane = tid & 31;
    const int warp_m = (wid & 3) * 32;   // 4 warps along M
    const int warp_n = (wid >> 2) * 64;  // 2 warps along N
    const int gr = lane >> 2;            // 0..7
    const int gc = lane & 3;             // 0..3

    const int bm = blockIdx.y * BM, bn = blockIdx.x * BN;

    // cp.async chunk assignment: 512 chunks of 16B per tile, 2 per thread
    const int c0row = (tid * 2) >> 2, c0seg = (tid * 2) & 3;
    const int c1row = (tid * 2 + 1) >> 2, c1seg = (tid * 2 + 1) & 3;

    const float* Abase = A + (size_t)bm * K;
    const float* Bbase = B + (size_t)bn * K;

#define PREFETCH(kt, buf) { \
    int k0 = (kt) * BK; \
    cp_async16(&As[buf][c0row][c0seg * 4], Abase + (size_t)c0row * K + k0 + c0seg * 4); \
    cp_async16(&As[buf][c1row][c1seg * 4], Abase + (size_t)c1row * K + k0 + c1seg * 4); \
    cp_async16(&Bs[buf][c0row][c0seg * 4], Bbase + (size_t)c0row * K + k0 + c0seg * 4); \
    cp_async16(&Bs[buf][c1row][c1seg * 4], Bbase + (size_t)c1row * K + k0 + c1seg * 4); \
    CP_COMMIT(); }

    float acc[2][8][4];
#pragma unroll
    for (int mt = 0; mt < 2; mt++)
#pragma unroll
        for (int nt = 0; nt < 8; nt++)
#pragma unroll
            for (int q = 0; q < 4; q++) acc[mt][nt][q] = 0.f;

    const int NT = K / BK;
    PREFETCH(0, 0)

    for (int kt = 0; kt < NT; kt++) {
        int buf = kt & 1;
        CP_WAIT0();
        __syncthreads();
        if (kt + 1 < NT) PREFETCH(kt + 1, buf ^ 1)

#pragma unroll
        for (int kk = 0; kk < BK; kk += 8) {
            uint32_t af[2][4], bf[8][2];
#pragma unroll
            for (int mt = 0; mt < 2; mt++) {
                int mb = warp_m + mt * 16;
                af[mt][0] = f2tf32(As[buf][mb + gr    ][kk + gc    ]);
                af[mt][1] = f2tf32(As[buf][mb + gr + 8][kk + gc    ]);
                af[mt][2] = f2tf32(As[buf][mb + gr    ][kk + gc + 4]);
                af[mt][3] = f2tf32(As[buf][mb + gr + 8][kk + gc + 4]);
            }
#pragma unroll
            for (int nt = 0; nt < 8; nt++) {
                int nb = warp_n + nt * 8;
                bf[nt][0] = f2tf32(Bs[buf][nb + gr][kk + gc    ]);
                bf[nt][1] = f2tf32(Bs[buf][nb + gr][kk + gc + 4]);
            }
#pragma unroll
            for (int mt = 0; mt < 2; mt++)
#pragma unroll
                for (int nt = 0; nt < 8; nt++) {
                    asm volatile(
                        "mma.sync.aligned.m16n8k8.row.col.f32.tf32.tf32.f32 "
                        "{%0,%1,%2,%3}, {%4,%5,%6,%7}, {%8,%9}, {%0,%1,%2,%3};"
                        : "+f"(acc[mt][nt][0]), "+f"(acc[mt][nt][1]),
                          "+f"(acc[mt][nt][2]), "+f"(acc[mt][nt][3])
                        : "r"(af[mt][0]), "r"(af[mt][1]), "r"(af[mt][2]), "r"(af[mt][3]),
                          "r"(bf[nt][0]), "r"(bf[nt][1]));
                }
        }
        __syncthreads();
    }
#undef PREFETCH

    // epilogue: c0,c1 contiguous (row, 2*gc), c2,c3 at row+8
#pragma unroll
    for (int mt = 0; mt < 2; mt++) {
#pragma unroll
        for (int nt = 0; nt < 8; nt++) {
            int row = bm + warp_m + mt * 16 + gr;
            int col = bn + warp_n + nt * 8 + 2 * gc;
#pragma unroll
            for (int half = 0; half < 2; half++) {
                size_t idx = (size_t)(row + half * 8) * N + col;
                float a0 = acc[mt][nt][half * 2 + 0];
                float a1 = acc[mt][nt][half * 2 + 1];
                float2 o;
                if (EP == 0)      { o.x = a0; o.y = a1; }
                else if (EP == 1) { o.x = a0 / (1.f + expf(-a0));
                                    o.y = a1 / (1.f + expf(-a1)); }
                else if (EP == 2) { float z0 = fmaxf(a0, 0.f), z1 = fmaxf(a1, 0.f);
                                    o.x = z0 * z0; o.y = z1 * z1; }
                else if (EP == 3) { o.x = 1.f / (1.f + expf(-a0));
                                    o.y = 1.f / (1.f + expf(-a1)); }
                else if (EP == 4) { float2 rr = *(const float2*)(res + idx);
                                    o.x = a0 + rr.x; o.y = a1 + rr.y; }
                else              { float2 cc = *(const float2*)(C + idx);
                                    float2 mm = *(const float2*)(mul + idx);
                                    o.x = cc.x + mm.x * a0; o.y = cc.y + mm.y * a1; }
                *(float2*)(C + idx) = o;
            }
        }
    }
}

// ---------------------------------------------------------------------------
// WKV5 recurrence (unchanged)
// ---------------------------------------------------------------------------
__global__ __launch_bounds__(256) void wkv_kernel(
    const float* __restrict__ r, const float* __restrict__ k,
    const float* __restrict__ v,
    const float* __restrict__ decay, const float* __restrict__ faaaa,
    float* __restrict__ y)
{
    const int CH = 8;
    __shared__ float sr[CH][Nv], sk[CH][Nv], sv[CH][Nv];

    int bh = blockIdx.x;
    int b = bh / Hv, h = bh % Hv;
    int tid = threadIdx.x;
    int j  = tid >> 2;
    int gq = tid & 3;
    int ib = gq * 16;

    float S[16], ew[16], uu[16];
#pragma unroll
    for (int ii = 0; ii < 16; ii++) {
        S[ii]  = 0.f;
        ew[ii] = expf(-expf(decay[h * Nv + ib + ii]));
        uu[ii] = faaaa[h * Nv + ib + ii];
    }

    size_t base = ((size_t)b * Tv) * Cv + (size_t)h * Nv;

    for (int tc = 0; tc < Tv; tc += CH) {
        __syncthreads();
        for (int idx = tid; idx < CH * Nv; idx += 256) {
            int st = idx >> 6, c = idx & 63;
            size_t off = base + (size_t)(tc + st) * Cv + c;
            sr[st][c] = r[off];
            sk[st][c] = k[off];
            sv[st][c] = v[off];
        }
        __syncthreads();

#pragma unroll
        for (int st = 0; st < CH; st++) {
            float vj = sv[st][j];
            float y0 = 0.f;
#pragma unroll
            for (int ii = 0; ii < 16; ii++) {
                float ri = sr[st][ib + ii];
                float ki = sk[st][ib + ii];
                float t = ki * vj;
                y0 = fmaf(ri, fmaf(uu[ii], t, S[ii]), y0);
                S[ii] = fmaf(ew[ii], S[ii], t);
            }
            y0 += __shfl_xor_sync(0xffffffffu, y0, 1);
            y0 += __shfl_xor_sync(0xffffffffu, y0, 2);
            if (gq == 0)
                y[base + (size_t)(tc + st) * Cv + j] = y0;
        }
    }
}

// ---------------------------------------------------------------------------
// GroupNorm * gate
// ---------------------------------------------------------------------------
__global__ __launch_bounds__(256) void gnmul_kernel(
    const float* __restrict__ y, const float* __restrict__ g,
    const float* __restrict__ w, const float* __restrict__ b,
    float* __restrict__ ym)
{
    int m = blockIdx.x, tid = threadIdx.x;
    size_t base = (size_t)m * Cv;
    float4 v = ((const float4*)(y + base))[tid];
    const float s8 = 1.0f / 8.0f;
    v.x *= s8; v.y *= s8; v.z *= s8; v.w *= s8;

    float s  = v.x + v.y + v.z + v.w;
    float ss = v.x*v.x + v.y*v.y + v.z*v.z + v.w*v.w;
#pragma unroll
    for (int o = 8; o; o >>= 1) {
        s  += __shfl_xor_sync(0xffffffffu, s,  o);
        ss += __shfl_xor_sync(0xffffffffu, ss, o);
    }
    float mu  = s * (1.0f / Nv);
    float var = ss * (1.0f / Nv) - mu * mu;
    float inv = rsqrtf(var + EPSv);

    float4 wv = ((const float4*)w)[tid];
    float4 bv = ((const float4*)b)[tid];
    float4 gv = ((const float4*)(g + base))[tid];
    float4 o;
    o.x = ((v.x - mu) * inv * wv.x + bv.x) * gv.x;
    o.y = ((v.y - mu) * inv * wv.y + bv.y) * gv.y;
    o.z = ((v.z - mu) * inv * wv.z + bv.z) * gv.z;
    o.w = ((v.w - mu) * inv * wv.w + bv.w) * gv.w;
    ((float4*)(ym + base))[tid] = o;
}

// ---------------------------------------------------------------------------
// launch
// ---------------------------------------------------------------------------
extern "C" void kernel_launch(void* const* d_in, const int* in_sizes, int n_in,
                              void* d_out, int out_size)
{
    const float* x        = (const float*)d_in[0];
    const float* ln0_w    = (const float*)d_in[1];
    const float* ln0_b    = (const float*)d_in[2];
    const float* ln1_w    = (const float*)d_in[3];
    const float* ln1_b    = (const float*)d_in[4];
    const float* ln2_w    = (const float*)d_in[5];
    const float* ln2_b    = (const float*)d_in[6];
    const float* att_tmk  = (const float*)d_in[7];
    const float* att_tmv  = (const float*)d_in[8];
    const float* att_tmr  = (const float*)d_in[9];
    const float* att_tmg  = (const float*)d_in[10];
    const float* att_decay  = (const float*)d_in[11];
    const float* att_faaaa  = (const float*)d_in[12];
    const float* att_Wr   = (const float*)d_in[13];
    const float* att_Wk   = (const float*)d_in[14];
    const float* att_Wv   = (const float*)d_in[15];
    const float* att_Wg   = (const float*)d_in[16];
    const float* att_Wo   = (const float*)d_in[17];
    const float* att_lnx_w = (const float*)d_in[18];
    const float* att_lnx_b = (const float*)d_in[19];
    const float* ffn_tmk  = (const float*)d_in[20];
    const float* ffn_tmr  = (const float*)d_in[21];
    const float* ffn_Wk   = (const float*)d_in[22];
    const float* ffn_Wr   = (const float*)d_in[23];
    const float* ffn_Wv   = (const float*)d_in[24];
    float* out = (float*)d_out;

    void* poolv = nullptr;
    cudaGetSymbolAddress(&poolv, g_pool);
    float* pool = (float*)poolv;

    float* bx0  = pool + OFF_X0;
    float* bxn  = pool + OFF_XN;
    float* bxr  = pool + OFF_XR;
    float* bxk  = pool + OFF_XK;
    float* bxv  = pool + OFF_XV;
    float* bxg  = pool + OFF_XG;
    float* br   = pool + OFF_R;
    float* bk   = pool + OFF_K;
    float* bv   = pool + OFF_V;
    float* bg   = pool + OFF_G;
    float* by   = pool + OFF_Y;
    float* bym  = pool + OFF_YM;
    float* bxn2 = pool + OFF_XN2;
    float* bxk2 = pool + OFF_XK2;
    float* bxr2 = pool + OFF_XR2;
    float* bsr  = pool + OFF_SR;
    float* bkf  = pool + OFF_KF;

    const int mixBlocks = (Mv * (Cv / 4)) / 256;      // 16384
    dim3 gC(Cv / 128, Mv / 128);                      // (8,128)
    dim3 gF(FFNv / 128, Mv / 128);                    // (28,128)

    // attention path
    ln01_kernel<<<Mv, 256>>>(x, ln0_w, ln0_b, ln1_w, ln1_b, bx0, bxn);
    mix4_kernel<<<mixBlocks, 256>>>(bxn, att_tmk, att_tmv, att_tmr, att_tmg,
                                    bxk, bxv, bxr, bxg);
    gemm_tf32<0><<<gC, 256>>>(bxr, att_Wr, br, Mv, Cv, Cv, nullptr, nullptr);
    gemm_tf32<0><<<gC, 256>>>(bxk, att_Wk, bk, Mv, Cv, Cv, nullptr, nullptr);
    gemm_tf32<0><<<gC, 256>>>(bxv, att_Wv, bv, Mv, Cv, Cv, nullptr, nullptr);
    gemm_tf32<1><<<gC, 256>>>(bxg, att_Wg, bg, Mv, Cv, Cv, nullptr, nullptr);  // silu
    wkv_kernel<<<Bv * Hv, 256>>>(br, bk, bv, att_decay, att_faaaa, by);
    gnmul_kernel<<<Mv, 256>>>(by, bg, att_lnx_w, att_lnx_b, bym);
    gemm_tf32<4><<<gC, 256>>>(bym, att_Wo, out, Mv, Cv, Cv, bx0, nullptr);    // +x0

    // channel-mix path
    ln_kernel<<<Mv, 256>>>(out, ln2_w, ln2_b, bxn2);
    mix2_kernel<<<mixBlocks, 256>>>(bxn2, ffn_tmk, ffn_tmr, bxk2, bxr2);
    gemm_tf32<2><<<gF, 256>>>(bxk2, ffn_Wk, bkf, Mv, FFNv, Cv, nullptr, nullptr); // relu^2
    gemm_tf32<3><<<gC, 256>>>(bxr2, ffn_Wr, bsr, Mv, Cv, Cv, nullptr, nullptr);   // sigmoid
    gemm_tf32<5><<<gC, 256>>>(bkf, ffn_Wv, out, Mv, Cv, FFNv, nullptr, bsr);      // out += sr*kv
}

// round 3
// speedup vs baseline: 2.2554x; 1.1435x over previous
#include <cuda_runtime.h>
#include <cstdint>
#include <math.h>

#define Bv   8
#define Tv   2048
#define Cv   1024
#define Hv   16
#define Nv   64
#define FFNv 3584
#define Mv   (Bv*Tv)          /* 16384 tokens */
#define EPSv 1e-5f

// ---------------------------------------------------------------------------
// Scratch pool (static device memory; no allocations anywhere).
// ---------------------------------------------------------------------------
#define MC   ((size_t)Mv * Cv)        /* 16,777,216 */
#define MF   ((size_t)Mv * FFNv)      /* 58,720,256 */
#define WCC  ((size_t)Cv * Cv)        /* 1,048,576  */
#define WFC  ((size_t)FFNv * Cv)      /* 3,670,016  */
// 16*MC + MF + 6*WCC + 2*WFC
__device__ float g_pool[16 * MC + MF + 6 * WCC + 2 * WFC];

#define OFF_X0   (0*MC)
#define OFF_XN   (1*MC)
#define OFF_XR   (2*MC)
#define OFF_XK   (3*MC)
#define OFF_XV   (4*MC)
#define OFF_XG   (5*MC)
#define OFF_R    (6*MC)
#define OFF_K    (7*MC)
#define OFF_V    (8*MC)
#define OFF_G    (9*MC)
#define OFF_Y    (10*MC)
#define OFF_YM   (11*MC)
#define OFF_XN2  (12*MC)
#define OFF_XK2  (13*MC)
#define OFF_XR2  (14*MC)
#define OFF_SR   (15*MC)
#define OFF_KF   (16*MC)
#define OFF_W    (16*MC + MF)         /* weight copies, tf32-rounded */
#define OFF_WR   (OFF_W + 0*WCC)
#define OFF_WK   (OFF_W + 1*WCC)
#define OFF_WV   (OFF_W + 2*WCC)
#define OFF_WG   (OFF_W + 3*WCC)
#define OFF_WO   (OFF_W + 4*WCC)
#define OFF_FWR  (OFF_W + 5*WCC)
#define OFF_FWK  (OFF_W + 6*WCC)
#define OFF_FWV  (OFF_W + 6*WCC + WFC)

// ---------------------------------------------------------------------------
// helpers
// ---------------------------------------------------------------------------
__device__ __forceinline__ float2 block_reduce2(float s, float ss, float* shm /*16*/)
{
#pragma unroll
    for (int o = 16; o; o >>= 1) {
        s  += __shfl_xor_sync(0xffffffffu, s,  o);
        ss += __shfl_xor_sync(0xffffffffu, ss, o);
    }
    int w = threadIdx.x >> 5;
    if ((threadIdx.x & 31) == 0) { shm[w] = s; shm[8 + w] = ss; }
    __syncthreads();
    s = shm[0]; ss = shm[8];
#pragma unroll
    for (int i = 1; i < 8; i++) { s += shm[i]; ss += shm[8 + i]; }
    return make_float2(s, ss);
}

__device__ __forceinline__ float tf32r(float x)
{
    asm("cvt.rna.tf32.f32 %0, %0;" : "+f"(x));
    return x;
}

__device__ __forceinline__ void cp_async16(void* smem, const void* gptr)
{
    unsigned saddr = (unsigned)__cvta_generic_to_shared(smem);
    asm volatile("cp.async.ca.shared.global [%0], [%1], 16;\n" :: "r"(saddr), "l"(gptr));
}
#define CP_COMMIT() asm volatile("cp.async.commit_group;\n" ::: "memory")
#define CP_WAIT0()  asm volatile("cp.async.wait_group 0;\n" ::: "memory")

#define LDSM4(r0, r1, r2, r3, addr) \
    asm volatile("ldmatrix.sync.aligned.m8n8.x4.shared.b16 {%0,%1,%2,%3}, [%4];" \
                 : "=r"(r0), "=r"(r1), "=r"(r2), "=r"(r3) : "r"(addr))

// ---------------------------------------------------------------------------
// weight tf32 pre-round (copy)
// ---------------------------------------------------------------------------
__global__ __launch_bounds__(256) void cvtw_kernel(
    const float* __restrict__ in, float* __restrict__ outp, int n4)
{
    int idx = blockIdx.x * blockDim.x + threadIdx.x;
    if (idx >= n4) return;
    float4 v = ((const float4*)in)[idx];
    v.x = tf32r(v.x); v.y = tf32r(v.y); v.z = tf32r(v.z); v.w = tf32r(v.w);
    ((float4*)outp)[idx] = v;
}

// ---------------------------------------------------------------------------
// LN0 + LN1 fused
// ---------------------------------------------------------------------------
__global__ __launch_bounds__(256) void ln01_kernel(
    const float* __restrict__ x,
    const float* __restrict__ w0, const float* __restrict__ b0,
    const float* __restrict__ w1, const float* __restrict__ b1,
    float* __restrict__ x0, float* __restrict__ xn)
{
    __shared__ float shm1[16], shm2[16];
    int m = blockIdx.x, tid = threadIdx.x;
    const float4 v = ((const float4*)(x + (size_t)m * Cv))[tid];

    float s  = v.x + v.y + v.z + v.w;
    float ss = v.x*v.x + v.y*v.y + v.z*v.z + v.w*v.w;
    float2 r = block_reduce2(s, ss, shm1);
    float mu  = r.x * (1.0f / Cv);
    float var = r.y * (1.0f / Cv) - mu * mu;
    float inv = rsqrtf(var + EPSv);

    const float4 wv0 = ((const float4*)w0)[tid];
    const float4 bv0 = ((const float4*)b0)[tid];
    float4 o;
    o.x = (v.x - mu) * inv * wv0.x + bv0.x;
    o.y = (v.y - mu) * inv * wv0.y + bv0.y;
    o.z = (v.z - mu) * inv * wv0.z + bv0.z;
    o.w = (v.w - mu) * inv * wv0.w + bv0.w;
    ((float4*)(x0 + (size_t)m * Cv))[tid] = o;

    s  = o.x + o.y + o.z + o.w;
    ss = o.x*o.x + o.y*o.y + o.z*o.z + o.w*o.w;
    r = block_reduce2(s, ss, shm2);
    mu  = r.x * (1.0f / Cv);
    var = r.y * (1.0f / Cv) - mu * mu;
    inv = rsqrtf(var + EPSv);

    const float4 wv1 = ((const float4*)w1)[tid];
    const float4 bv1 = ((const float4*)b1)[tid];
    float4 o2;
    o2.x = (o.x - mu) * inv * wv1.x + bv1.x;
    o2.y = (o.y - mu) * inv * wv1.y + bv1.y;
    o2.z = (o.z - mu) * inv * wv1.z + bv1.z;
    o2.w = (o.w - mu) * inv * wv1.w + bv1.w;
    ((float4*)(xn + (size_t)m * Cv))[tid] = o2;
}

__global__ __launch_bounds__(256) void ln_kernel(
    const float* __restrict__ in,
    const float* __restrict__ w, const float* __restrict__ b,
    float* __restrict__ outp)
{
    __shared__ float shm[16];
    int m = blockIdx.x, tid = threadIdx.x;
    const float4 v = ((const float4*)(in + (size_t)m * Cv))[tid];
    float s  = v.x + v.y + v.z + v.w;
    float ss = v.x*v.x + v.y*v.y + v.z*v.z + v.w*v.w;
    float2 r = block_reduce2(s, ss, shm);
    float mu  = r.x * (1.0f / Cv);
    float var = r.y * (1.0f / Cv) - mu * mu;
    float inv = rsqrtf(var + EPSv);
    const float4 wv = ((const float4*)w)[tid];
    const float4 bv = ((const float4*)b)[tid];
    float4 o;
    o.x = (v.x - mu) * inv * wv.x + bv.x;
    o.y = (v.y - mu) * inv * wv.y + bv.y;
    o.z = (v.z - mu) * inv * wv.z + bv.z;
    o.w = (v.w - mu) * inv * wv.w + bv.w;
    ((float4*)(outp + (size_t)m * Cv))[tid] = o;
}

// ---------------------------------------------------------------------------
// token-shift mix (outputs tf32-rounded: they only feed GEMM A operands)
// ---------------------------------------------------------------------------
__global__ __launch_bounds__(256) void mix4_kernel(
    const float* __restrict__ xn,
    const float* __restrict__ tmk, const float* __restrict__ tmv,
    const float* __restrict__ tmr, const float* __restrict__ tmg,
    float* __restrict__ xk, float* __restrict__ xv,
    float* __restrict__ xr, float* __restrict__ xg)
{
    const int C4 = Cv / 4;
    int idx = blockIdx.x * blockDim.x + threadIdx.x;
    int m  = idx / C4;
    int c4 = idx - m * C4;
    float4 a = ((const float4*)xn)[idx];
    float4 p = make_float4(0.f, 0.f, 0.f, 0.f);
    if ((m % Tv) != 0) p = ((const float4*)xn)[idx - C4];
    float4 d = make_float4(a.x - p.x, a.y - p.y, a.z - p.z, a.w - p.w);

#define DO_MIX(TM, OUT) { \
    float4 w = ((const float4*)TM)[c4]; \
    float4 o; \
    o.x = tf32r(fmaf(d.x, w.x, p.x)); o.y = tf32r(fmaf(d.y, w.y, p.y)); \
    o.z = tf32r(fmaf(d.z, w.z, p.z)); o.w = tf32r(fmaf(d.w, w.w, p.w)); \
    ((float4*)OUT)[idx] = o; }

    DO_MIX(tmk, xk)
    DO_MIX(tmv, xv)
    DO_MIX(tmr, xr)
    DO_MIX(tmg, xg)
#undef DO_MIX
}

__global__ __launch_bounds__(256) void mix2_kernel(
    const float* __restrict__ xn,
    const float* __restrict__ tmk, const float* __restrict__ tmr,
    float* __restrict__ xk, float* __restrict__ xr)
{
    const int C4 = Cv / 4;
    int idx = blockIdx.x * blockDim.x + threadIdx.x;
    int m  = idx / C4;
    int c4 = idx - m * C4;
    float4 a = ((const float4*)xn)[idx];
    float4 p = make_float4(0.f, 0.f, 0.f, 0.f);
    if ((m % Tv) != 0) p = ((const float4*)xn)[idx - C4];
    float4 d = make_float4(a.x - p.x, a.y - p.y, a.z - p.z, a.w - p.w);
#define DO_MIX(TM, OUT) { \
    float4 w = ((const float4*)TM)[c4]; \
    float4 o; \
    o.x = tf32r(fmaf(d.x, w.x, p.x)); o.y = tf32r(fmaf(d.y, w.y, p.y)); \
    o.z = tf32r(fmaf(d.z, w.z, p.z)); o.w = tf32r(fmaf(d.w, w.w, p.w)); \
    ((float4*)OUT)[idx] = o; }
    DO_MIX(tmk, xk)
    DO_MIX(tmr, xr)
#undef DO_MIX
}

// ---------------------------------------------------------------------------
// TF32 tensor-core NT GEMM with ldmatrix fragment loads.
// C[M,N] = A[M,K] @ B[N,K]^T, 128x128x16 CTA tile, 8 warps of 32x64.
// Inputs must be pre-rounded to tf32.
// Epilogues: 0 none, 1 silu, 2 relu^2 (tf32-rounded out), 3 sigmoid,
//            4 +res, 5 C += mul*acc
// ---------------------------------------------------------------------------
template<int EP>
__global__ __launch_bounds__(256) void gemm_tf32(
    const float* __restrict__ A, const float* __restrict__ B,
    float* __restrict__ C, int M, int N, int K,
    const float* __restrict__ res, const float* __restrict__ mul)
{
    const int BM = 128, BN = 128, BK = 16, P = 20;
    __shared__ float As[2][BM][P];
    __shared__ float Bs[2][BN][P];

    const int tid  = threadIdx.x;
    const int wid  = tid >> 5;
    const int lane = tid & 31;
    const int warp_m = (wid & 3) * 32;   // 4 warps along M
    const int warp_n = (wid >> 2) * 64;  // 2 warps along N
    const int gr = lane >> 2;            // 0..7
    const int gc = lane & 3;             // 0..3

    const int bm = blockIdx.y * BM, bn = blockIdx.x * BN;

    // cp.async chunk assignment: 512 chunks of 16B per tile, 2 per thread
    const int c0row = (tid * 2) >> 2, c0seg = (tid * 2) & 3;
    const int c1row = (tid * 2 + 1) >> 2, c1seg = (tid * 2 + 1) & 3;

    const float* Abase = A + (size_t)bm * K;
    const float* Bbase = B + (size_t)bn * K;

    // ldmatrix per-lane base addresses (byte offsets in smem space)
    const unsigned asmem = (unsigned)__cvta_generic_to_shared(&As[0][0][0]);
    const unsigned bsmem = (unsigned)__cvta_generic_to_shared(&Bs[0][0][0]);
    // A: row = warp_m + (lane&15), col = (lane&16)>>2
    const unsigned aoff = asmem + (unsigned)(((warp_m + (lane & 15)) * P + ((lane & 16) >> 2)) * 4);
    // B: row = warp_n + (lane&7) + ((lane&16)>>1), col = (lane&8)>>1
    const unsigned boff = bsmem + (unsigned)(((warp_n + (lane & 7) + ((lane & 16) >> 1)) * P + ((lane & 8) >> 1)) * 4);
    const unsigned BUFA = BM * P * 4;     // bytes per A buffer
    const unsigned BUFB = BN * P * 4;
    const unsigned R16  = 16 * P * 4;     // 16 rows stride

#define PREFETCH(kt, buf) { \
    int k0 = (kt) * BK; \
    cp_async16(&As[buf][c0row][c0seg * 4], Abase + (size_t)c0row * K + k0 + c0seg * 4); \
    cp_async16(&As[buf][c1row][c1seg * 4], Abase + (size_t)c1row * K + k0 + c1seg * 4); \
    cp_async16(&Bs[buf][c0row][c0seg * 4], Bbase + (size_t)c0row * K + k0 + c0seg * 4); \
    cp_async16(&Bs[buf][c1row][c1seg * 4], Bbase + (size_t)c1row * K + k0 + c1seg * 4); \
    CP_COMMIT(); }

    float acc[2][8][4];
#pragma unroll
    for (int mt = 0; mt < 2; mt++)
#pragma unroll
        for (int nt = 0; nt < 8; nt++)
#pragma unroll
            for (int q = 0; q < 4; q++) acc[mt][nt][q] = 0.f;

    const int NT = K / BK;
    PREFETCH(0, 0)

    for (int kt = 0; kt < NT; kt++) {
        int buf = kt & 1;
        CP_WAIT0();
        __syncthreads();
        if (kt + 1 < NT) PREFETCH(kt + 1, buf ^ 1)

        const unsigned ab = aoff + buf * BUFA;
        const unsigned bb = boff + buf * BUFB;
#pragma unroll
        for (int kk = 0; kk < BK; kk += 8) {
            uint32_t af[2][4], bf[8][2];
#pragma unroll
            for (int mt = 0; mt < 2; mt++)
                LDSM4(af[mt][0], af[mt][1], af[mt][2], af[mt][3],
                      ab + mt * R16 + kk * 4);
#pragma unroll
            for (int p = 0; p < 4; p++)
                LDSM4(bf[2*p][0], bf[2*p][1], bf[2*p+1][0], bf[2*p+1][1],
                      bb + p * R16 + kk * 4);
#pragma unroll
            for (int mt = 0; mt < 2; mt++)
#pragma unroll
                for (int nt = 0; nt < 8; nt++) {
                    asm volatile(
                        "mma.sync.aligned.m16n8k8.row.col.f32.tf32.tf32.f32 "
                        "{%0,%1,%2,%3}, {%4,%5,%6,%7}, {%8,%9}, {%0,%1,%2,%3};"
                        : "+f"(acc[mt][nt][0]), "+f"(acc[mt][nt][1]),
                          "+f"(acc[mt][nt][2]), "+f"(acc[mt][nt][3])
                        : "r"(af[mt][0]), "r"(af[mt][1]), "r"(af[mt][2]), "r"(af[mt][3]),
                          "r"(bf[nt][0]), "r"(bf[nt][1]));
                }
        }
        __syncthreads();
    }
#undef PREFETCH

    // epilogue: c0,c1 contiguous (row, 2*gc), c2,c3 at row+8
#pragma unroll
    for (int mt = 0; mt < 2; mt++) {
#pragma unroll
        for (int nt = 0; nt < 8; nt++) {
            int row = bm + warp_m + mt * 16 + gr;
            int col = bn + warp_n + nt * 8 + 2 * gc;
#pragma unroll
            for (int half = 0; half < 2; half++) {
                size_t idx = (size_t)(row + half * 8) * N + col;
                float a0 = acc[mt][nt][half * 2 + 0];
                float a1 = acc[mt][nt][half * 2 + 1];
                float2 o;
                if (EP == 0)      { o.x = a0; o.y = a1; }
                else if (EP == 1) { o.x = a0 / (1.f + expf(-a0));
                                    o.y = a1 / (1.f + expf(-a1)); }
                else if (EP == 2) { float z0 = fmaxf(a0, 0.f), z1 = fmaxf(a1, 0.f);
                                    o.x = tf32r(z0 * z0); o.y = tf32r(z1 * z1); }
                else if (EP == 3) { o.x = 1.f / (1.f + expf(-a0));
                                    o.y = 1.f / (1.f + expf(-a1)); }
                else if (EP == 4) { float2 rr = *(const float2*)(res + idx);
                                    o.x = a0 + rr.x; o.y = a1 + rr.y; }
                else              { float2 cc = *(const float2*)(C + idx);
                                    float2 mm = *(const float2*)(mul + idx);
                                    o.x = cc.x + mm.x * a0; o.y = cc.y + mm.y * a1; }
                *(float2*)(C + idx) = o;
            }
        }
    }
}

// ---------------------------------------------------------------------------
// WKV5 recurrence
// ---------------------------------------------------------------------------
__global__ __launch_bounds__(256) void wkv_kernel(
    const float* __restrict__ r, const float* __restrict__ k,
    const float* __restrict__ v,
    const float* __restrict__ decay, const float* __restrict__ faaaa,
    float* __restrict__ y)
{
    const int CH = 8;
    __shared__ float sr[CH][Nv], sk[CH][Nv], sv[CH][Nv];

    int bh = blockIdx.x;
    int b = bh / Hv, h = bh % Hv;
    int tid = threadIdx.x;
    int j  = tid >> 2;
    int gq = tid & 3;
    int ib = gq * 16;

    float S[16], ew[16], uu[16];
#pragma unroll
    for (int ii = 0; ii < 16; ii++) {
        S[ii]  = 0.f;
        ew[ii] = expf(-expf(decay[h * Nv + ib + ii]));
        uu[ii] = faaaa[h * Nv + ib + ii];
    }

    size_t base = ((size_t)b * Tv) * Cv + (size_t)h * Nv;

    for (int tc = 0; tc < Tv; tc += CH) {
        __syncthreads();
        for (int idx = tid; idx < CH * Nv; idx += 256) {
            int st = idx >> 6, c = idx & 63;
            size_t off = base + (size_t)(tc + st) * Cv + c;
            sr[st][c] = r[off];
            sk[st][c] = k[off];
            sv[st][c] = v[off];
        }
        __syncthreads();

#pragma unroll
        for (int st = 0; st < CH; st++) {
            float vj = sv[st][j];
            float y0 = 0.f;
#pragma unroll
            for (int ii = 0; ii < 16; ii++) {
                float ri = sr[st][ib + ii];
                float ki = sk[st][ib + ii];
                float t = ki * vj;
                y0 = fmaf(ri, fmaf(uu[ii], t, S[ii]), y0);
                S[ii] = fmaf(ew[ii], S[ii], t);
            }
            y0 += __shfl_xor_sync(0xffffffffu, y0, 1);
            y0 += __shfl_xor_sync(0xffffffffu, y0, 2);
            if (gq == 0)
                y[base + (size_t)(tc + st) * Cv + j] = y0;
        }
    }
}

// ---------------------------------------------------------------------------
// GroupNorm * gate (output tf32-rounded: feeds Wo GEMM)
// ---------------------------------------------------------------------------
__global__ __launch_bounds__(256) void gnmul_kernel(
    const float* __restrict__ y, const float* __restrict__ g,
    const float* __restrict__ w, const float* __restrict__ b,
    float* __restrict__ ym)
{
    int m = blockIdx.x, tid = threadIdx.x;
    size_t base = (size_t)m * Cv;
    float4 v = ((const float4*)(y + base))[tid];
    const float s8 = 1.0f / 8.0f;
    v.x *= s8; v.y *= s8; v.z *= s8; v.w *= s8;

    float s  = v.x + v.y + v.z + v.w;
    float ss = v.x*v.x + v.y*v.y + v.z*v.z + v.w*v.w;
#pragma unroll
    for (int o = 8; o; o >>= 1) {
        s  += __shfl_xor_sync(0xffffffffu, s,  o);
        ss += __shfl_xor_sync(0xffffffffu, ss, o);
    }
    float mu  = s * (1.0f / Nv);
    float var = ss * (1.0f / Nv) - mu * mu;
    float inv = rsqrtf(var + EPSv);

    float4 wv = ((const float4*)w)[tid];
    float4 bv = ((const float4*)b)[tid];
    float4 gv = ((const float4*)(g + base))[tid];
    float4 o;
    o.x = tf32r(((v.x - mu) * inv * wv.x + bv.x) * gv.x);
    o.y = tf32r(((v.y - mu) * inv * wv.y + bv.y) * gv.y);
    o.z = tf32r(((v.z - mu) * inv * wv.z + bv.z) * gv.z);
    o.w = tf32r(((v.w - mu) * inv * wv.w + bv.w) * gv.w);
    ((float4*)(ym + base))[tid] = o;
}

// ---------------------------------------------------------------------------
// launch
// ---------------------------------------------------------------------------
extern "C" void kernel_launch(void* const* d_in, const int* in_sizes, int n_in,
                              void* d_out, int out_size)
{
    const float* x        = (const float*)d_in[0];
    const float* ln0_w    = (const float*)d_in[1];
    const float* ln0_b    = (const float*)d_in[2];
    const float* ln1_w    = (const float*)d_in[3];
    const float* ln1_b    = (const float*)d_in[4];
    const float* ln2_w    = (const float*)d_in[5];
    const float* ln2_b    = (const float*)d_in[6];
    const float* att_tmk  = (const float*)d_in[7];
    const float* att_tmv  = (const float*)d_in[8];
    const float* att_tmr  = (const float*)d_in[9];
    const float* att_tmg  = (const float*)d_in[10];
    const float* att_decay  = (const float*)d_in[11];
    const float* att_faaaa  = (const float*)d_in[12];
    const float* att_Wr   = (const float*)d_in[13];
    const float* att_Wk   = (const float*)d_in[14];
    const float* att_Wv   = (const float*)d_in[15];
    const float* att_Wg   = (const float*)d_in[16];
    const float* att_Wo   = (const float*)d_in[17];
    const float* att_lnx_w = (const float*)d_in[18];
    const float* att_lnx_b = (const float*)d_in[19];
    const float* ffn_tmk  = (const float*)d_in[20];
    const float* ffn_tmr  = (const float*)d_in[21];
    const float* ffn_Wk   = (const float*)d_in[22];
    const float* ffn_Wr   = (const float*)d_in[23];
    const float* ffn_Wv   = (const float*)d_in[24];
    float* out = (float*)d_out;

    void* poolv = nullptr;
    cudaGetSymbolAddress(&poolv, g_pool);
    float* pool = (float*)poolv;

    float* bx0  = pool + OFF_X0;
    float* bxn  = pool + OFF_XN;
    float* bxr  = pool + OFF_XR;
    float* bxk  = pool + OFF_XK;
    float* bxv  = pool + OFF_XV;
    float* bxg  = pool + OFF_XG;
    float* br   = pool + OFF_R;
    float* bk   = pool + OFF_K;
    float* bv   = pool + OFF_V;
    float* bg   = pool + OFF_G;
    float* by   = pool + OFF_Y;
    float* bym  = pool + OFF_YM;
    float* bxn2 = pool + OFF_XN2;
    float* bxk2 = pool + OFF_XK2;
    float* bxr2 = pool + OFF_XR2;
    float* bsr  = pool + OFF_SR;
    float* bkf  = pool + OFF_KF;
    float* wWr  = pool + OFF_WR;
    float* wWk  = pool + OFF_WK;
    float* wWv  = pool + OFF_WV;
    float* wWg  = pool + OFF_WG;
    float* wWo  = pool + OFF_WO;
    float* wFWr = pool + OFF_FWR;
    float* wFWk = pool + OFF_FWK;
    float* wFWv = pool + OFF_FWV;

    const int mixBlocks = (Mv * (Cv / 4)) / 256;      // 16384
    dim3 gC(Cv / 128, Mv / 128);                      // (8,128)
    dim3 gF(FFNv / 128, Mv / 128);                    // (28,128)

    // weight tf32 pre-round
    const int nCC4 = (int)(WCC / 4), nFC4 = (int)(WFC / 4);
    cvtw_kernel<<<(nCC4 + 255) / 256, 256>>>(att_Wr, wWr, nCC4);
    cvtw_kernel<<<(nCC4 + 255) / 256, 256>>>(att_Wk, wWk, nCC4);
    cvtw_kernel<<<(nCC4 + 255) / 256, 256>>>(att_Wv, wWv, nCC4);
    cvtw_kernel<<<(nCC4 + 255) / 256, 256>>>(att_Wg, wWg, nCC4);
    cvtw_kernel<<<(nCC4 + 255) / 256, 256>>>(att_Wo, wWo, nCC4);
    cvtw_kernel<<<(nCC4 + 255) / 256, 256>>>(ffn_Wr, wFWr, nCC4);
    cvtw_kernel<<<(nFC4 + 255) / 256, 256>>>(ffn_Wk, wFWk, nFC4);
    cvtw_kernel<<<(nFC4 + 255) / 256, 256>>>(ffn_Wv, wFWv, nFC4);

    // attention path
    ln01_kernel<<<Mv, 256>>>(x, ln0_w, ln0_b, ln1_w, ln1_b, bx0, bxn);
    mix4_kernel<<<mixBlocks, 256>>>(bxn, att_tmk, att_tmv, att_tmr, att_tmg,
                                    bxk, bxv, bxr, bxg);
    gemm_tf32<0><<<gC, 256>>>(bxr, wWr, br, Mv, Cv, Cv, nullptr, nullptr);
    gemm_tf32<0><<<gC, 256>>>(bxk, wWk, bk, Mv, Cv, Cv, nullptr, nullptr);
    gemm_tf32<0><<<gC, 256>>>(bxv, wWv, bv, Mv, Cv, Cv, nullptr, nullptr);
    gemm_tf32<1><<<gC, 256>>>(bxg, wWg, bg, Mv, Cv, Cv, nullptr, nullptr);  // silu
    wkv_kernel<<<Bv * Hv, 256>>>(br, bk, bv, att_decay, att_faaaa, by);
    gnmul_kernel<<<Mv, 256>>>(by, bg, att_lnx_w, att_lnx_b, bym);
    gemm_tf32<4><<<gC, 256>>>(bym, wWo, out, Mv, Cv, Cv, bx0, nullptr);    // +x0

    // channel-mix path
    ln_kernel<<<Mv, 256>>>(out, ln2_w, ln2_b, bxn2);
    mix2_kernel<<<mixBlocks, 256>>>(bxn2, ffn_tmk, ffn_tmr, bxk2, bxr2);
    gemm_tf32<2><<<gF, 256>>>(bxk2, wFWk, bkf, Mv, FFNv, Cv, nullptr, nullptr); // relu^2
    gemm_tf32<3><<<gC, 256>>>(bxr2, wFWr, bsr, Mv, Cv, Cv, nullptr, nullptr);   // sigmoid
    gemm_tf32<5><<<gC, 256>>>(bkf, wFWv, out, Mv, Cv, FFNv, nullptr, bsr);      // out += sr*kv
}

// round 5
// speedup vs baseline: 2.8474x; 1.2625x over previous
#include <cuda_runtime.h>
#include <cstdint>
#include <math.h>

#define Bv   8
#define Tv   2048
#define Cv   1024
#define Hv   16
#define Nv   64
#define FFNv 3584
#define Mv   (Bv*Tv)          /* 16384 tokens */
#define EPSv 1e-5f

// ---------------------------------------------------------------------------
// Scratch pool (static device memory; no allocations anywhere).
// ---------------------------------------------------------------------------
#define MC   ((size_t)Mv * Cv)        /* 16,777,216 */
#define MF   ((size_t)Mv * FFNv)      /* 58,720,256 */
#define WCC  ((size_t)Cv * Cv)        /* 1,048,576  */
#define WFC  ((size_t)FFNv * Cv)      /* 3,670,016  */
__device__ float g_pool[16 * MC + MF + 6 * WCC + 2 * WFC];

#define OFF_X0   (0*MC)
#define OFF_XN   (1*MC)
#define OFF_XR   (2*MC)
#define OFF_XK   (3*MC)
#define OFF_XV   (4*MC)
#define OFF_XG   (5*MC)
#define OFF_R    (6*MC)
#define OFF_K    (7*MC)
#define OFF_V    (8*MC)
#define OFF_G    (9*MC)
#define OFF_Y    (10*MC)
#define OFF_YM   (11*MC)
#define OFF_XN2  (12*MC)
#define OFF_XK2  (13*MC)
#define OFF_XR2  (14*MC)
#define OFF_SR   (15*MC)
#define OFF_KF   (16*MC)
#define OFF_W    (16*MC + MF)
#define OFF_WR   (OFF_W + 0*WCC)
#define OFF_WK   (OFF_W + 1*WCC)
#define OFF_WV   (OFF_W + 2*WCC)
#define OFF_WG   (OFF_W + 3*WCC)
#define OFF_WO   (OFF_W + 4*WCC)
#define OFF_FWR  (OFF_W + 5*WCC)
#define OFF_FWK  (OFF_W + 6*WCC)
#define OFF_FWV  (OFF_W + 6*WCC + WFC)

// ---------------------------------------------------------------------------
// helpers
// ---------------------------------------------------------------------------
__device__ __forceinline__ float2 block_reduce2(float s, float ss, float* shm /*16*/)
{
#pragma unroll
    for (int o = 16; o; o >>= 1) {
        s  += __shfl_xor_sync(0xffffffffu, s,  o);
        ss += __shfl_xor_sync(0xffffffffu, ss, o);
    }
    int w = threadIdx.x >> 5;
    if ((threadIdx.x & 31) == 0) { shm[w] = s; shm[8 + w] = ss; }
    __syncthreads();
    s = shm[0]; ss = shm[8];
#pragma unroll
    for (int i = 1; i < 8; i++) { s += shm[i]; ss += shm[8 + i]; }
    return make_float2(s, ss);
}

__device__ __forceinline__ float tf32r(float x)
{
    asm("cvt.rna.tf32.f32 %0, %0;" : "+f"(x));
    return x;
}

__device__ __forceinline__ void cp_async16(void* smem, const void* gptr)
{
    unsigned saddr = (unsigned)__cvta_generic_to_shared(smem);
    asm volatile("cp.async.ca.shared.global [%0], [%1], 16;\n" :: "r"(saddr), "l"(gptr));
}
#define CP_COMMIT() asm volatile("cp.async.commit_group;\n" ::: "memory")
#define CP_WAIT0()  asm volatile("cp.async.wait_group 0;\n" ::: "memory")

#define LDSM4(r0, r1, r2, r3, addr) \
    asm volatile("ldmatrix.sync.aligned.m8n8.x4.shared.b16 {%0,%1,%2,%3}, [%4];" \
                 : "=r"(r0), "=r"(r1), "=r"(r2), "=r"(r3) : "r"(addr))

// ---------------------------------------------------------------------------
// weight tf32 pre-round
// ---------------------------------------------------------------------------
__global__ __launch_bounds__(256) void cvtw_kernel(
    const float* __restrict__ in, float* __restrict__ outp, int n4)
{
    int idx = blockIdx.x * blockDim.x + threadIdx.x;
    if (idx >= n4) return;
    float4 v = ((const float4*)in)[idx];
    v.x = tf32r(v.x); v.y = tf32r(v.y); v.z = tf32r(v.z); v.w = tf32r(v.w);
    ((float4*)outp)[idx] = v;
}

// ---------------------------------------------------------------------------
// LN0 + LN1 fused
// ---------------------------------------------------------------------------
__global__ __launch_bounds__(256) void ln01_kernel(
    const float* __restrict__ x,
    const float* __restrict__ w0, const float* __restrict__ b0,
    const float* __restrict__ w1, const float* __restrict__ b1,
    float* __restrict__ x0, float* __restrict__ xn)
{
    __shared__ float shm1[16], shm2[16];
    int m = blockIdx.x, tid = threadIdx.x;
    const float4 v = ((const float4*)(x + (size_t)m * Cv))[tid];

    float s  = v.x + v.y + v.z + v.w;
    float ss = v.x*v.x + v.y*v.y + v.z*v.z + v.w*v.w;
    float2 r = block_reduce2(s, ss, shm1);
    float mu  = r.x * (1.0f / Cv);
    float var = r.y * (1.0f / Cv) - mu * mu;
    float inv = rsqrtf(var + EPSv);

    const float4 wv0 = ((const float4*)w0)[tid];
    const float4 bv0 = ((const float4*)b0)[tid];
    float4 o;
    o.x = (v.x - mu) * inv * wv0.x + bv0.x;
    o.y = (v.y - mu) * inv * wv0.y + bv0.y;
    o.z = (v.z - mu) * inv * wv0.z + bv0.z;
    o.w = (v.w - mu) * inv * wv0.w + bv0.w;
    ((float4*)(x0 + (size_t)m * Cv))[tid] = o;

    s  = o.x + o.y + o.z + o.w;
    ss = o.x*o.x + o.y*o.y + o.z*o.z + o.w*o.w;
    r = block_reduce2(s, ss, shm2);
    mu  = r.x * (1.0f / Cv);
    var = r.y * (1.0f / Cv) - mu * mu;
    inv = rsqrtf(var + EPSv);

    const float4 wv1 = ((const float4*)w1)[tid];
    const float4 bv1 = ((const float4*)b1)[tid];
    float4 o2;
    o2.x = (o.x - mu) * inv * wv1.x + bv1.x;
    o2.y = (o.y - mu) * inv * wv1.y + bv1.y;
    o2.z = (o.z - mu) * inv * wv1.z + bv1.z;
    o2.w = (o.w - mu) * inv * wv1.w + bv1.w;
    ((float4*)(xn + (size_t)m * Cv))[tid] = o2;
}

__global__ __launch_bounds__(256) void ln_kernel(
    const float* __restrict__ in,
    const float* __restrict__ w, const float* __restrict__ b,
    float* __restrict__ outp)
{
    __shared__ float shm[16];
    int m = blockIdx.x, tid = threadIdx.x;
    const float4 v = ((const float4*)(in + (size_t)m * Cv))[tid];
    float s  = v.x + v.y + v.z + v.w;
    float ss = v.x*v.x + v.y*v.y + v.z*v.z + v.w*v.w;
    float2 r = block_reduce2(s, ss, shm);
    float mu  = r.x * (1.0f / Cv);
    float var = r.y * (1.0f / Cv) - mu * mu;
    float inv = rsqrtf(var + EPSv);
    const float4 wv = ((const float4*)w)[tid];
    const float4 bv = ((const float4*)b)[tid];
    float4 o;
    o.x = (v.x - mu) * inv * wv.x + bv.x;
    o.y = (v.y - mu) * inv * wv.y + bv.y;
    o.z = (v.z - mu) * inv * wv.z + bv.z;
    o.w = (v.w - mu) * inv * wv.w + bv.w;
    ((float4*)(outp + (size_t)m * Cv))[tid] = o;
}

// ---------------------------------------------------------------------------
// token-shift mix (outputs tf32-rounded)
// ---------------------------------------------------------------------------
__global__ __launch_bounds__(256) void mix4_kernel(
    const float* __restrict__ xn,
    const float* __restrict__ tmk, const float* __restrict__ tmv,
    const float* __restrict__ tmr, const float* __restrict__ tmg,
    float* __restrict__ xk, float* __restrict__ xv,
    float* __restrict__ xr, float* __restrict__ xg)
{
    const int C4 = Cv / 4;
    int idx = blockIdx.x * blockDim.x + threadIdx.x;
    int m  = idx / C4;
    int c4 = idx - m * C4;
    float4 a = ((const float4*)xn)[idx];
    float4 p = make_float4(0.f, 0.f, 0.f, 0.f);
    if ((m % Tv) != 0) p = ((const float4*)xn)[idx - C4];
    float4 d = make_float4(a.x - p.x, a.y - p.y, a.z - p.z, a.w - p.w);

#define DO_MIX(TM, OUT) { \
    float4 w = ((const float4*)TM)[c4]; \
    float4 o; \
    o.x = tf32r(fmaf(d.x, w.x, p.x)); o.y = tf32r(fmaf(d.y, w.y, p.y)); \
    o.z = tf32r(fmaf(d.z, w.z, p.z)); o.w = tf32r(fmaf(d.w, w.w, p.w)); \
    ((float4*)OUT)[idx] = o; }

    DO_MIX(tmk, xk)
    DO_MIX(tmv, xv)
    DO_MIX(tmr, xr)
    DO_MIX(tmg, xg)
#undef DO_MIX
}

__global__ __launch_bounds__(256) void mix2_kernel(
    const float* __restrict__ xn,
    const float* __restrict__ tmk, const float* __restrict__ tmr,
    float* __restrict__ xk, float* __restrict__ xr)
{
    const int C4 = Cv / 4;
    int idx = blockIdx.x * blockDim.x + threadIdx.x;
    int m  = idx / C4;
    int c4 = idx - m * C4;
    float4 a = ((const float4*)xn)[idx];
    float4 p = make_float4(0.f, 0.f, 0.f, 0.f);
    if ((m % Tv) != 0) p = ((const float4*)xn)[idx - C4];
    float4 d = make_float4(a.x - p.x, a.y - p.y, a.z - p.z, a.w - p.w);
#define DO_MIX(TM, OUT) { \
    float4 w = ((const float4*)TM)[c4]; \
    float4 o; \
    o.x = tf32r(fmaf(d.x, w.x, p.x)); o.y = tf32r(fmaf(d.y, w.y, p.y)); \
    o.z = tf32r(fmaf(d.z, w.z, p.z)); o.w = tf32r(fmaf(d.w, w.w, p.w)); \
    ((float4*)OUT)[idx] = o; }
    DO_MIX(tmk, xk)
    DO_MIX(tmr, xr)
#undef DO_MIX
}

// ---------------------------------------------------------------------------
// TF32 tensor-core NT GEMM, CTA tile 128x256x32, 8 warps of 64x64.
// Dynamic smem: As[2][128][36], Bs[2][256][36] floats (110,592 B).
// Inputs pre-rounded to tf32.
// Epilogues: 0 none, 1 silu, 2 relu^2(tf32), 3 sigmoid, 4 +res, 5 C+=mul*acc
// ---------------------------------------------------------------------------
template<int EP>
__global__ __launch_bounds__(256, 1) void gemm_tf32(
    const float* __restrict__ A, const float* __restrict__ B,
    float* __restrict__ C, int M, int N, int K,
    const float* __restrict__ res, const float* __restrict__ mul)
{
    const int BM = 128, BN = 256, BK = 32, P = 36;
    extern __shared__ float smem[];
    float* As = smem;                       // [2][128][36]
    float* Bs = smem + 2 * BM * P;          // [2][256][36]

    const int tid  = threadIdx.x;
    const int wid  = tid >> 5;
    const int lane = tid & 31;
    const int warp_m = (wid & 1) * 64;      // 2 warps along M
    const int warp_n = (wid >> 1) * 64;     // 4 warps along N
    const int gr = lane >> 2;               // 0..7
    const int gc = lane & 3;                // 0..3

    const int bm = blockIdx.y * BM, bn = blockIdx.x * BN;

    const float* Abase = A + (size_t)bm * K;
    const float* Bbase = B + (size_t)bn * K;

    const unsigned asmem = (unsigned)__cvta_generic_to_shared(As);
    const unsigned bsmem = (unsigned)__cvta_generic_to_shared(Bs);
    const unsigned aoff = asmem + (unsigned)(((warp_m + (lane & 15)) * P + ((lane & 16) >> 2)) * 4);
    const unsigned boff = bsmem + (unsigned)(((warp_n + (lane & 7) + ((lane & 16) >> 1)) * P + ((lane & 8) >> 1)) * 4);
    const unsigned BUFA = BM * P * 4;       // bytes per A stage
    const unsigned BUFB = BN * P * 4;       // bytes per B stage
    const unsigned R16  = 16 * P * 4;

    // cp.async: A = 1024 chunks (4/thread), B = 2048 chunks (8/thread)
    const int arow = tid >> 3;              // base rows for c=0
    const int aseg = tid & 7;

#define PREFETCH(kt, buf) { \
    int k0 = (kt) * BK; \
    _Pragma("unroll") \
    for (int c = 0; c < 4; c++) { \
        int row = arow + c * 32; \
        cp_async16(As + (buf) * BM * P + row * P + aseg * 4, \
                   Abase + (size_t)row * K + k0 + aseg * 4); \
    } \
    _Pragma("unroll") \
    for (int c = 0; c < 8; c++) { \
        int row = arow + c * 32; \
        cp_async16(Bs + (buf) * BN * P + row * P + aseg * 4, \
                   Bbase + (size_t)row * K + k0 + aseg * 4); \
    } \
    CP_COMMIT(); }

    float acc[4][8][4];
#pragma unroll
    for (int mt = 0; mt < 4; mt++)
#pragma unroll
        for (int nt = 0; nt < 8; nt++)
#pragma unroll
            for (int q = 0; q < 4; q++) acc[mt][nt][q] = 0.f;

    const int NT = K / BK;
    PREFETCH(0, 0)

    for (int kt = 0; kt < NT; kt++) {
        int buf = kt & 1;
        CP_WAIT0();
        __syncthreads();
        if (kt + 1 < NT) PREFETCH(kt + 1, buf ^ 1)

        const unsigned ab = aoff + buf * BUFA;
        const unsigned bb = boff + buf * BUFB;
#pragma unroll
        for (int kk = 0; kk < BK; kk += 8) {
            uint32_t af[4][4], bf[8][2];
#pragma unroll
            for (int mt = 0; mt < 4; mt++)
                LDSM4(af[mt][0], af[mt][1], af[mt][2], af[mt][3],
                      ab + mt * R16 + kk * 4);
#pragma unroll
            for (int p = 0; p < 4; p++)
                LDSM4(bf[2*p][0], bf[2*p][1], bf[2*p+1][0], bf[2*p+1][1],
                      bb + p * R16 + kk * 4);
#pragma unroll
            for (int mt = 0; mt < 4; mt++)
#pragma unroll
                for (int nt = 0; nt < 8; nt++) {
                    asm volatile(
                        "mma.sync.aligned.m16n8k8.row.col.f32.tf32.tf32.f32 "
                        "{%0,%1,%2,%3}, {%4,%5,%6,%7}, {%8,%9}, {%0,%1,%2,%3};"
                        : "+f"(acc[mt][nt][0]), "+f"(acc[mt][nt][1]),
                          "+f"(acc[mt][nt][2]), "+f"(acc[mt][nt][3])
                        : "r"(af[mt][0]), "r"(af[mt][1]), "r"(af[mt][2]), "r"(af[mt][3]),
                          "r"(bf[nt][0]), "r"(bf[nt][1]));
                }
        }
        __syncthreads();
    }
#undef PREFETCH

#pragma unroll
    for (int mt = 0; mt < 4; mt++) {
#pragma unroll
        for (int nt = 0; nt < 8; nt++) {
            int row = bm + warp_m + mt * 16 + gr;
            int col = bn + warp_n + nt * 8 + 2 * gc;
#pragma unroll
            for (int half = 0; half < 2; half++) {
                size_t idx = (size_t)(row + half * 8) * N + col;
                float a0 = acc[mt][nt][half * 2 + 0];
                float a1 = acc[mt][nt][half * 2 + 1];
                float2 o;
                if (EP == 0)      { o.x = a0; o.y = a1; }
                else if (EP == 1) { o.x = a0 / (1.f + expf(-a0));
                                    o.y = a1 / (1.f + expf(-a1)); }
                else if (EP == 2) { float z0 = fmaxf(a0, 0.f), z1 = fmaxf(a1, 0.f);
                                    o.x = tf32r(z0 * z0); o.y = tf32r(z1 * z1); }
                else if (EP == 3) { o.x = 1.f / (1.f + expf(-a0));
                                    o.y = 1.f / (1.f + expf(-a1)); }
                else if (EP == 4) { float2 rr = *(const float2*)(res + idx);
                                    o.x = a0 + rr.x; o.y = a1 + rr.y; }
                else              { float2 cc = *(const float2*)(C + idx);
                                    float2 mm = *(const float2*)(mul + idx);
                                    o.x = cc.x + mm.x * a0; o.y = cc.y + mm.y * a1; }
                *(float2*)(C + idx) = o;
            }
        }
    }
}

// ---------------------------------------------------------------------------
// WKV5 recurrence
// ---------------------------------------------------------------------------
__global__ __launch_bounds__(256) void wkv_kernel(
    const float* __restrict__ r, const float* __restrict__ k,
    const float* __restrict__ v,
    const float* __restrict__ decay, const float* __restrict__ faaaa,
    float* __restrict__ y)
{
    const int CH = 8;
    __shared__ float sr[CH][Nv], sk[CH][Nv], sv[CH][Nv];

    int bh = blockIdx.x;
    int b = bh / Hv, h = bh % Hv;
    int tid = threadIdx.x;
    int j  = tid >> 2;
    int gq = tid & 3;
    int ib = gq * 16;

    float S[16], ew[16], uu[16];
#pragma unroll
    for (int ii = 0; ii < 16; ii++) {
        S[ii]  = 0.f;
        ew[ii] = expf(-expf(decay[h * Nv + ib + ii]));
        uu[ii] = faaaa[h * Nv + ib + ii];
    }

    size_t base = ((size_t)b * Tv) * Cv + (size_t)h * Nv;

    for (int tc = 0; tc < Tv; tc += CH) {
        __syncthreads();
        for (int idx = tid; idx < CH * Nv; idx += 256) {
            int st = idx >> 6, c = idx & 63;
            size_t off = base + (size_t)(tc + st) * Cv + c;
            sr[st][c] = r[off];
            sk[st][c] = k[off];
            sv[st][c] = v[off];
        }
        __syncthreads();

#pragma unroll
        for (int st = 0; st < CH; st++) {
            float vj = sv[st][j];
            float y0 = 0.f;
#pragma unroll
            for (int ii = 0; ii < 16; ii++) {
                float ri = sr[st][ib + ii];
                float ki = sk[st][ib + ii];
                float t = ki * vj;
                y0 = fmaf(ri, fmaf(uu[ii], t, S[ii]), y0);
                S[ii] = fmaf(ew[ii], S[ii], t);
            }
            y0 += __shfl_xor_sync(0xffffffffu, y0, 1);
            y0 += __shfl_xor_sync(0xffffffffu, y0, 2);
            if (gq == 0)
                y[base + (size_t)(tc + st) * Cv + j] = y0;
        }
    }
}

// ---------------------------------------------------------------------------
// GroupNorm * gate (output tf32-rounded)
// ---------------------------------------------------------------------------
__global__ __launch_bounds__(256) void gnmul_kernel(
    const float* __restrict__ y, const float* __restrict__ g,
    const float* __restrict__ w, const float* __restrict__ b,
    float* __restrict__ ym)
{
    int m = blockIdx.x, tid = threadIdx.x;
    size_t base = (size_t)m * Cv;
    float4 v = ((const float4*)(y + base))[tid];
    const float s8 = 1.0f / 8.0f;
    v.x *= s8; v.y *= s8; v.z *= s8; v.w *= s8;

    float s  = v.x + v.y + v.z + v.w;
    float ss = v.x*v.x + v.y*v.y + v.z*v.z + v.w*v.w;
#pragma unroll
    for (int o = 8; o; o >>= 1) {
        s  += __shfl_xor_sync(0xffffffffu, s,  o);
        ss += __shfl_xor_sync(0xffffffffu, ss, o);
    }
    float mu  = s * (1.0f / Nv);
    float var = ss * (1.0f / Nv) - mu * mu;
    float inv = rsqrtf(var + EPSv);

    float4 wv = ((const float4*)w)[tid];
    float4 bv = ((const float4*)b)[tid];
    float4 gv = ((const float4*)(g + base))[tid];
    float4 o;
    o.x = tf32r(((v.x - mu) * inv * wv.x + bv.x) * gv.x);
    o.y = tf32r(((v.y - mu) * inv * wv.y + bv.y) * gv.y);
    o.z = tf32r(((v.z - mu) * inv * wv.z + bv.z) * gv.z);
    o.w = tf32r(((v.w - mu) * inv * wv.w + bv.w) * gv.w);
    ((float4*)(ym + base))[tid] = o;
}

// ---------------------------------------------------------------------------
// launch
// ---------------------------------------------------------------------------
#define GEMM_SMEM (2 * (128 * 36 + 256 * 36) * 4)   /* 110,592 B */

extern "C" void kernel_launch(void* const* d_in, const int* in_sizes, int n_in,
                              void* d_out, int out_size)
{
    const float* x        = (const float*)d_in[0];
    const float* ln0_w    = (const float*)d_in[1];
    const float* ln0_b    = (const float*)d_in[2];
    const float* ln1_w    = (const float*)d_in[3];
    const float* ln1_b    = (const float*)d_in[4];
    const float* ln2_w    = (const float*)d_in[5];
    const float* ln2_b    = (const float*)d_in[6];
    const float* att_tmk  = (const float*)d_in[7];
    const float* att_tmv  = (const float*)d_in[8];
    const float* att_tmr  = (const float*)d_in[9];
    const float* att_tmg  = (const float*)d_in[10];
    const float* att_decay  = (const float*)d_in[11];
    const float* att_faaaa  = (const float*)d_in[12];
    const float* att_Wr   = (const float*)d_in[13];
    const float* att_Wk   = (const float*)d_in[14];
    const float* att_Wv   = (const float*)d_in[15];
    const float* att_Wg   = (const float*)d_in[16];
    const float* att_Wo   = (const float*)d_in[17];
    const float* att_lnx_w = (const float*)d_in[18];
    const float* att_lnx_b = (const float*)d_in[19];
    const float* ffn_tmk  = (const float*)d_in[20];
    const float* ffn_tmr  = (const float*)d_in[21];
    const float* ffn_Wk   = (const float*)d_in[22];
    const float* ffn_Wr   = (const float*)d_in[23];
    const float* ffn_Wv   = (const float*)d_in[24];
    float* out = (float*)d_out;

    void* poolv = nullptr;
    cudaGetSymbolAddress(&poolv, g_pool);
    float* pool = (float*)poolv;

    float* bx0  = pool + OFF_X0;
    float* bxn  = pool + OFF_XN;
    float* bxr  = pool + OFF_XR;
    float* bxk  = pool + OFF_XK;
    float* bxv  = pool + OFF_XV;
    float* bxg  = pool + OFF_XG;
    float* br   = pool + OFF_R;
    float* bk   = pool + OFF_K;
    float* bv   = pool + OFF_V;
    float* bg   = pool + OFF_G;
    float* by   = pool + OFF_Y;
    float* bym  = pool + OFF_YM;
    float* bxn2 = pool + OFF_XN2;
    float* bxk2 = pool + OFF_XK2;
    float* bxr2 = pool + OFF_XR2;
    float* bsr  = pool + OFF_SR;
    float* bkf  = pool + OFF_KF;
    float* wWr  = pool + OFF_WR;
    float* wWk  = pool + OFF_WK;
    float* wWv  = pool + OFF_WV;
    float* wWg  = pool + OFF_WG;
    float* wWo  = pool + OFF_WO;
    float* wFWr = pool + OFF_FWR;
    float* wFWk = pool + OFF_FWK;
    float* wFWv = pool + OFF_FWV;

    // allow 110.6 KB dynamic smem (idempotent)
    cudaFuncSetAttribute(gemm_tf32<0>, cudaFuncAttributeMaxDynamicSharedMemorySize, GEMM_SMEM);
    cudaFuncSetAttribute(gemm_tf32<1>, cudaFuncAttributeMaxDynamicSharedMemorySize, GEMM_SMEM);
    cudaFuncSetAttribute(gemm_tf32<2>, cudaFuncAttributeMaxDynamicSharedMemorySize, GEMM_SMEM);
    cudaFuncSetAttribute(gemm_tf32<3>, cudaFuncAttributeMaxDynamicSharedMemorySize, GEMM_SMEM);
    cudaFuncSetAttribute(gemm_tf32<4>, cudaFuncAttributeMaxDynamicSharedMemorySize, GEMM_SMEM);
    cudaFuncSetAttribute(gemm_tf32<5>, cudaFuncAttributeMaxDynamicSharedMemorySize, GEMM_SMEM);

    const int mixBlocks = (Mv * (Cv / 4)) / 256;      // 16384
    dim3 gC(Cv / 256, Mv / 128);                      // (4,128)
    dim3 gF(FFNv / 256, Mv / 128);                    // (14,128)

    // weight tf32 pre-round
    const int nCC4 = (int)(WCC / 4), nFC4 = (int)(WFC / 4);
    cvtw_kernel<<<(nCC4 + 255) / 256, 256>>>(att_Wr, wWr, nCC4);
    cvtw_kernel<<<(nCC4 + 255) / 256, 256>>>(att_Wk, wWk, nCC4);
    cvtw_kernel<<<(nCC4 + 255) / 256, 256>>>(att_Wv, wWv, nCC4);
    cvtw_kernel<<<(nCC4 + 255) / 256, 256>>>(att_Wg, wWg, nCC4);
    cvtw_kernel<<<(nCC4 + 255) / 256, 256>>>(att_Wo, wWo, nCC4);
    cvtw_kernel<<<(nCC4 + 255) / 256, 256>>>(ffn_Wr, wFWr, nCC4);
    cvtw_kernel<<<(nFC4 + 255) / 256, 256>>>(ffn_Wk, wFWk, nFC4);
    cvtw_kernel<<<(nFC4 + 255) / 256, 256>>>(ffn_Wv, wFWv, nFC4);

    // attention path
    ln01_kernel<<<Mv, 256>>>(x, ln0_w, ln0_b, ln1_w, ln1_b, bx0, bxn);
    mix4_kernel<<<mixBlocks, 256>>>(bxn, att_tmk, att_tmv, att_tmr, att_tmg,
                                    bxk, bxv, bxr, bxg);
    gemm_tf32<0><<<gC, 256, GEMM_SMEM>>>(bxr, wWr, br, Mv, Cv, Cv, nullptr, nullptr);
    gemm_tf32<0><<<gC, 256, GEMM_SMEM>>>(bxk, wWk, bk, Mv, Cv, Cv, nullptr, nullptr);
    gemm_tf32<0><<<gC, 256, GEMM_SMEM>>>(bxv, wWv, bv, Mv, Cv, Cv, nullptr, nullptr);
    gemm_tf32<1><<<gC, 256, GEMM_SMEM>>>(bxg, wWg, bg, Mv, Cv, Cv, nullptr, nullptr);
    wkv_kernel<<<Bv * Hv, 256>>>(br, bk, bv, att_decay, att_faaaa, by);
    gnmul_kernel<<<Mv, 256>>>(by, bg, att_lnx_w, att_lnx_b, bym);
    gemm_tf32<4><<<gC, 256, GEMM_SMEM>>>(bym, wWo, out, Mv, Cv, Cv, bx0, nullptr);

    // channel-mix path
    ln_kernel<<<Mv, 256>>>(out, ln2_w, ln2_b, bxn2);
    mix2_kernel<<<mixBlocks, 256>>>(bxn2, ffn_tmk, ffn_tmr, bxk2, bxr2);
    gemm_tf32<2><<<gF, 256, GEMM_SMEM>>>(bxk2, wFWk, bkf, Mv, FFNv, Cv, nullptr, nullptr);
    gemm_tf32<3><<<gC, 256, GEMM_SMEM>>>(bxr2, wFWr, bsr, Mv, Cv, Cv, nullptr, nullptr);
    gemm_tf32<5><<<gC, 256, GEMM_SMEM>>>(bkf, wFWv, out, Mv, Cv, FFNv, nullptr, bsr);
}

// round 6
// speedup vs baseline: 2.9775x; 1.0457x over previous
#include <cuda_runtime.h>
#include <cstdint>
#include <math.h>

#define Bv   8
#define Tv   2048
#define Cv   1024
#define Hv   16
#define Nv   64
#define FFNv 3584
#define Mv   (Bv*Tv)          /* 16384 tokens */
#define EPSv 1e-5f

// ---------------------------------------------------------------------------
// Scratch pool (static device memory; no allocations anywhere).
// ---------------------------------------------------------------------------
#define MC   ((size_t)Mv * Cv)        /* 16,777,216 */
#define MF   ((size_t)Mv * FFNv)      /* 58,720,256 */
#define WCC  ((size_t)Cv * Cv)        /* 1,048,576  */
#define WFC  ((size_t)FFNv * Cv)      /* 3,670,016  */
__device__ float g_pool[16 * MC + MF + 6 * WCC + 2 * WFC];

#define OFF_X0   (0*MC)
#define OFF_XR   (2*MC)
#define OFF_XK   (3*MC)
#define OFF_XV   (4*MC)
#define OFF_XG   (5*MC)
#define OFF_R    (6*MC)
#define OFF_K    (7*MC)
#define OFF_V    (8*MC)
#define OFF_G    (9*MC)
#define OFF_Y    (10*MC)
#define OFF_YM   (11*MC)
#define OFF_XK2  (13*MC)
#define OFF_XR2  (14*MC)
#define OFF_SR   (15*MC)
#define OFF_KF   (16*MC)
#define OFF_W    (16*MC + MF)
#define OFF_WR   (OFF_W + 0*WCC)
#define OFF_WK   (OFF_W + 1*WCC)
#define OFF_WV   (OFF_W + 2*WCC)
#define OFF_WG   (OFF_W + 3*WCC)
#define OFF_WO   (OFF_W + 4*WCC)
#define OFF_FWR  (OFF_W + 5*WCC)
#define OFF_FWK  (OFF_W + 6*WCC)
#define OFF_FWV  (OFF_W + 6*WCC + WFC)

// ---------------------------------------------------------------------------
// helpers
// ---------------------------------------------------------------------------
__device__ __forceinline__ float4 block_reduce4(float a, float b, float c, float d,
                                                float* shm /*32*/)
{
#pragma unroll
    for (int o = 16; o; o >>= 1) {
        a += __shfl_xor_sync(0xffffffffu, a, o);
        b += __shfl_xor_sync(0xffffffffu, b, o);
        c += __shfl_xor_sync(0xffffffffu, c, o);
        d += __shfl_xor_sync(0xffffffffu, d, o);
    }
    int w = threadIdx.x >> 5;
    if ((threadIdx.x & 31) == 0) { shm[w] = a; shm[8+w] = b; shm[16+w] = c; shm[24+w] = d; }
    __syncthreads();
    a = shm[0]; b = shm[8]; c = shm[16]; d = shm[24];
#pragma unroll
    for (int i = 1; i < 8; i++) {
        a += shm[i]; b += shm[8+i]; c += shm[16+i]; d += shm[24+i];
    }
    return make_float4(a, b, c, d);
}

__device__ __forceinline__ float tf32r(float x)
{
    asm("cvt.rna.tf32.f32 %0, %0;" : "+f"(x));
    return x;
}

__device__ __forceinline__ void cp_async16(void* smem, const void* gptr)
{
    unsigned saddr = (unsigned)__cvta_generic_to_shared(smem);
    asm volatile("cp.async.ca.shared.global [%0], [%1], 16;\n" :: "r"(saddr), "l"(gptr));
}
#define CP_COMMIT() asm volatile("cp.async.commit_group;\n" ::: "memory")
#define CP_WAIT0()  asm volatile("cp.async.wait_group 0;\n" ::: "memory")
#define CP_WAIT1()  asm volatile("cp.async.wait_group 1;\n" ::: "memory")

#define LDSM4(r0, r1, r2, r3, addr) \
    asm volatile("ldmatrix.sync.aligned.m8n8.x4.shared.b16 {%0,%1,%2,%3}, [%4];" \
                 : "=r"(r0), "=r"(r1), "=r"(r2), "=r"(r3) : "r"(addr))

// ---------------------------------------------------------------------------
// weight tf32 pre-round
// ---------------------------------------------------------------------------
__global__ __launch_bounds__(256) void cvtw_kernel(
    const float* __restrict__ in, float* __restrict__ outp, int n4)
{
    int idx = blockIdx.x * blockDim.x + threadIdx.x;
    if (idx >= n4) return;
    float4 v = ((const float4*)in)[idx];
    v.x = tf32r(v.x); v.y = tf32r(v.y); v.z = tf32r(v.z); v.w = tf32r(v.w);
    ((float4*)outp)[idx] = v;
}

// ---------------------------------------------------------------------------
// Fused LN0+LN1+token-shift-mix4 (attention front).
// Block per token; recompute prev token's LN chain to avoid xn round-trip.
// ---------------------------------------------------------------------------
__global__ __launch_bounds__(256) void ln01mix4_kernel(
    const float* __restrict__ x,
    const float* __restrict__ w0, const float* __restrict__ b0,
    const float* __restrict__ w1, const float* __restrict__ b1,
    const float* __restrict__ tmk, const float* __restrict__ tmv,
    const float* __restrict__ tmr, const float* __restrict__ tmg,
    float* __restrict__ x0,
    float* __restrict__ xk, float* __restrict__ xv,
    float* __restrict__ xr, float* __restrict__ xg)
{
    __shared__ float shm1[32], shm2[32];
    int m = blockIdx.x, tid = threadIdx.x;
    bool hp = (m % Tv) != 0;

    const float4 vc = ((const float4*)(x + (size_t)m * Cv))[tid];
    float4 vp = make_float4(0.f, 0.f, 0.f, 0.f);
    if (hp) vp = ((const float4*)(x + (size_t)(m - 1) * Cv))[tid];

    float4 r0 = block_reduce4(
        vc.x + vc.y + vc.z + vc.w,
        vc.x*vc.x + vc.y*vc.y + vc.z*vc.z + vc.w*vc.w,
        vp.x + vp.y + vp.z + vp.w,
        vp.x*vp.x + vp.y*vp.y + vp.z*vp.z + vp.w*vp.w, shm1);

    float muc = r0.x * (1.0f / Cv);
    float ivc = rsqrtf(r0.y * (1.0f / Cv) - muc * muc + EPSv);
    float mup = r0.z * (1.0f / Cv);
    float ivp = rsqrtf(r0.w * (1.0f / Cv) - mup * mup + EPSv);

    const float4 w0v = ((const float4*)w0)[tid];
    const float4 b0v = ((const float4*)b0)[tid];
    float4 c0, p0;
    c0.x = (vc.x - muc) * ivc * w0v.x + b0v.x;
    c0.y = (vc.y - muc) * ivc * w0v.y + b0v.y;
    c0.z = (vc.z - muc) * ivc * w0v.z + b0v.z;
    c0.w = (vc.w - muc) * ivc * w0v.w + b0v.w;
    p0.x = (vp.x - mup) * ivp * w0v.x + b0v.x;
    p0.y = (vp.y - mup) * ivp * w0v.y + b0v.y;
    p0.z = (vp.z - mup) * ivp * w0v.z + b0v.z;
    p0.w = (vp.w - mup) * ivp * w0v.w + b0v.w;
    ((float4*)(x0 + (size_t)m * Cv))[tid] = c0;

    float4 r1 = block_reduce4(
        c0.x + c0.y + c0.z + c0.w,
        c0.x*c0.x + c0.y*c0.y + c0.z*c0.z + c0.w*c0.w,
        p0.x + p0.y + p0.z + p0.w,
        p0.x*p0.x + p0.y*p0.y + p0.z*p0.z + p0.w*p0.w, shm2);

    muc = r1.x * (1.0f / Cv);
    ivc = rsqrtf(r1.y * (1.0f / Cv) - muc * muc + EPSv);
    mup = r1.z * (1.0f / Cv);
    ivp = rsqrtf(r1.w * (1.0f / Cv) - mup * mup + EPSv);

    const float4 w1v = ((const float4*)w1)[tid];
    const float4 b1v = ((const float4*)b1)[tid];
    float4 xnc, xnp;
    xnc.x = (c0.x - muc) * ivc * w1v.x + b1v.x;
    xnc.y = (c0.y - muc) * ivc * w1v.y + b1v.y;
    xnc.z = (c0.z - muc) * ivc * w1v.z + b1v.z;
    xnc.w = (c0.w - muc) * ivc * w1v.w + b1v.w;
    if (hp) {
        xnp.x = (p0.x - mup) * ivp * w1v.x + b1v.x;
        xnp.y = (p0.y - mup) * ivp * w1v.y + b1v.y;
        xnp.z = (p0.z - mup) * ivp * w1v.z + b1v.z;
        xnp.w = (p0.w - mup) * ivp * w1v.w + b1v.w;
    } else {
        xnp = make_float4(0.f, 0.f, 0.f, 0.f);
    }
    float4 dd = make_float4(xnc.x - xnp.x, xnc.y - xnp.y,
                            xnc.z - xnp.z, xnc.w - xnp.w);
    size_t idx = (size_t)m * (Cv / 4) + tid;

#define DO_MIX(TM, OUT) { \
    float4 w = ((const float4*)TM)[tid]; \
    float4 o; \
    o.x = tf32r(fmaf(dd.x, w.x, xnp.x)); o.y = tf32r(fmaf(dd.y, w.y, xnp.y)); \
    o.z = tf32r(fmaf(dd.z, w.z, xnp.z)); o.w = tf32r(fmaf(dd.w, w.w, xnp.w)); \
    ((float4*)OUT)[idx] = o; }

    DO_MIX(tmk, xk)
    DO_MIX(tmv, xv)
    DO_MIX(tmr, xr)
    DO_MIX(tmg, xg)
#undef DO_MIX
}

// ---------------------------------------------------------------------------
// Fused LN2+token-shift-mix2 (channel-mix front)
// ---------------------------------------------------------------------------
__global__ __launch_bounds__(256) void ln2mix2_kernel(
    const float* __restrict__ in,
    const float* __restrict__ w2, const float* __restrict__ b2,
    const float* __restrict__ tmk, const float* __restrict__ tmr,
    float* __restrict__ xk, float* __restrict__ xr)
{
    __shared__ float shm[32];
    int m = blockIdx.x, tid = threadIdx.x;
    bool hp = (m % Tv) != 0;

    const float4 vc = ((const float4*)(in + (size_t)m * Cv))[tid];
    float4 vp = make_float4(0.f, 0.f, 0.f, 0.f);
    if (hp) vp = ((const float4*)(in + (size_t)(m - 1) * Cv))[tid];

    float4 r0 = block_reduce4(
        vc.x + vc.y + vc.z + vc.w,
        vc.x*vc.x + vc.y*vc.y + vc.z*vc.z + vc.w*vc.w,
        vp.x + vp.y + vp.z + vp.w,
        vp.x*vp.x + vp.y*vp.y + vp.z*vp.z + vp.w*vp.w, shm);

    float muc = r0.x * (1.0f / Cv);
    float ivc = rsqrtf(r0.y * (1.0f / Cv) - muc * muc + EPSv);
    float mup = r0.z * (1.0f / Cv);
    float ivp = rsqrtf(r0.w * (1.0f / Cv) - mup * mup + EPSv);

    const float4 wv = ((const float4*)w2)[tid];
    const float4 bv = ((const float4*)b2)[tid];
    float4 xnc, xnp;
    xnc.x = (vc.x - muc) * ivc * wv.x + bv.x;
    xnc.y = (vc.y - muc) * ivc * wv.y + bv.y;
    xnc.z = (vc.z - muc) * ivc * wv.z + bv.z;
    xnc.w = (vc.w - muc) * ivc * wv.w + bv.w;
    if (hp) {
        xnp.x = (vp.x - mup) * ivp * wv.x + bv.x;
        xnp.y = (vp.y - mup) * ivp * wv.y + bv.y;
        xnp.z = (vp.z - mup) * ivp * wv.z + bv.z;
        xnp.w = (vp.w - mup) * ivp * wv.w + bv.w;
    } else {
        xnp = make_float4(0.f, 0.f, 0.f, 0.f);
    }
    float4 dd = make_float4(xnc.x - xnp.x, xnc.y - xnp.y,
                            xnc.z - xnp.z, xnc.w - xnp.w);
    size_t idx = (size_t)m * (Cv / 4) + tid;

#define DO_MIX(TM, OUT) { \
    float4 w = ((const float4*)TM)[tid]; \
    float4 o; \
    o.x = tf32r(fmaf(dd.x, w.x, xnp.x)); o.y = tf32r(fmaf(dd.y, w.y, xnp.y)); \
    o.z = tf32r(fmaf(dd.z, w.z, xnp.z)); o.w = tf32r(fmaf(dd.w, w.w, xnp.w)); \
    ((float4*)OUT)[idx] = o; }

    DO_MIX(tmk, xk)
    DO_MIX(tmr, xr)
#undef DO_MIX
}

// ---------------------------------------------------------------------------
// TF32 tensor-core NT GEMM core, CTA tile 128x256x32, 8 warps of 64x64.
// 3-stage cp.async pipeline, one __syncthreads per k-iter.
// EP: 0 none, 1 silu, 2 relu^2(tf32), 3 sigmoid, 4 +res, 5 C+=mul*acc,
//     6 runtime rt_ep in {0 none,1 silu,2 relu^2,3 sigmoid}
// ---------------------------------------------------------------------------
template<int EP>
__device__ __forceinline__ void gemm_core(
    const float* __restrict__ A, const float* __restrict__ B,
    float* __restrict__ C, int M, int N, int K,
    const float* __restrict__ res, const float* __restrict__ mul,
    int rt_ep, float* smem, int bm, int bn)
{
    const int BM = 128, BN = 256, BK = 32, P = 36;
    float* As = smem;                       // [3][128][36]
    float* Bs = smem + 3 * BM * P;          // [3][256][36]

    const int tid  = threadIdx.x;
    const int wid  = tid >> 5;
    const int lane = tid & 31;
    const int warp_m = (wid & 1) * 64;
    const int warp_n = (wid >> 1) * 64;
    const int gr = lane >> 2;
    const int gc = lane & 3;

    const float* Abase = A + (size_t)bm * K;
    const float* Bbase = B + (size_t)bn * K;

    const unsigned asmem = (unsigned)__cvta_generic_to_shared(As);
    const unsigned bsmem = (unsigned)__cvta_generic_to_shared(Bs);
    const unsigned aoff = asmem + (unsigned)(((warp_m + (lane & 15)) * P + ((lane & 16) >> 2)) * 4);
    const unsigned boff = bsmem + (unsigned)(((warp_n + (lane & 7) + ((lane & 16) >> 1)) * P + ((lane & 8) >> 1)) * 4);
    const unsigned BUFA = BM * P * 4;
    const unsigned BUFB = BN * P * 4;
    const unsigned R16  = 16 * P * 4;

    const int arow = tid >> 3;
    const int aseg = tid & 7;

#define PREFETCH(kt, buf) { \
    int k0 = (kt) * BK; \
    _Pragma("unroll") \
    for (int c = 0; c < 4; c++) { \
        int row = arow + c * 32; \
        cp_async16(As + (buf) * BM * P + row * P + aseg * 4, \
                   Abase + (size_t)row * K + k0 + aseg * 4); \
    } \
    _Pragma("unroll") \
    for (int c = 0; c < 8; c++) { \
        int row = arow + c * 32; \
        cp_async16(Bs + (buf) * BN * P + row * P + aseg * 4, \
                   Bbase + (size_t)row * K + k0 + aseg * 4); \
    } \
    CP_COMMIT(); }

    float acc[4][8][4];
#pragma unroll
    for (int mt = 0; mt < 4; mt++)
#pragma unroll
        for (int nt = 0; nt < 8; nt++)
#pragma unroll
            for (int q = 0; q < 4; q++) acc[mt][nt][q] = 0.f;

    const int NT = K / BK;
    PREFETCH(0, 0)
    PREFETCH(1, 1)

    int buf = 0;
    for (int kt = 0; kt < NT; kt++) {
        if (kt + 1 < NT) { CP_WAIT1(); } else { CP_WAIT0(); }
        __syncthreads();
        int nbuf = buf + 2; if (nbuf >= 3) nbuf -= 3;
        if (kt + 2 < NT) PREFETCH(kt + 2, nbuf)

        const unsigned ab = aoff + buf * BUFA;
        const unsigned bb = boff + buf * BUFB;
#pragma unroll
        for (int kk = 0; kk < BK; kk += 8) {
            uint32_t af[4][4], bf[8][2];
#pragma unroll
            for (int mt = 0; mt < 4; mt++)
                LDSM4(af[mt][0], af[mt][1], af[mt][2], af[mt][3],
                      ab + mt * R16 + kk * 4);
#pragma unroll
            for (int p = 0; p < 4; p++)
                LDSM4(bf[2*p][0], bf[2*p][1], bf[2*p+1][0], bf[2*p+1][1],
                      bb + p * R16 + kk * 4);
#pragma unroll
            for (int mt = 0; mt < 4; mt++)
#pragma unroll
                for (int nt = 0; nt < 8; nt++) {
                    asm volatile(
                        "mma.sync.aligned.m16n8k8.row.col.f32.tf32.tf32.f32 "
                        "{%0,%1,%2,%3}, {%4,%5,%6,%7}, {%8,%9}, {%0,%1,%2,%3};"
                        : "+f"(acc[mt][nt][0]), "+f"(acc[mt][nt][1]),
                          "+f"(acc[mt][nt][2]), "+f"(acc[mt][nt][3])
                        : "r"(af[mt][0]), "r"(af[mt][1]), "r"(af[mt][2]), "r"(af[mt][3]),
                          "r"(bf[nt][0]), "r"(bf[nt][1]));
                }
        }
        buf = buf + 1; if (buf >= 3) buf -= 3;
    }
#undef PREFETCH

#pragma unroll
    for (int mt = 0; mt < 4; mt++) {
#pragma unroll
        for (int nt = 0; nt < 8; nt++) {
            int row = bm + warp_m + mt * 16 + gr;
            int col = bn + warp_n + nt * 8 + 2 * gc;
#pragma unroll
            for (int half = 0; half < 2; half++) {
                size_t idx = (size_t)(row + half * 8) * N + col;
                float a0 = acc[mt][nt][half * 2 + 0];
                float a1 = acc[mt][nt][half * 2 + 1];
                float2 o;
                if (EP == 0)      { o.x = a0; o.y = a1; }
                else if (EP == 1) { o.x = a0 / (1.f + expf(-a0));
                                    o.y = a1 / (1.f + expf(-a1)); }
                else if (EP == 2) { float z0 = fmaxf(a0, 0.f), z1 = fmaxf(a1, 0.f);
                                    o.x = tf32r(z0 * z0); o.y = tf32r(z1 * z1); }
                else if (EP == 3) { o.x = 1.f / (1.f + expf(-a0));
                                    o.y = 1.f / (1.f + expf(-a1)); }
                else if (EP == 4) { float2 rr = *(const float2*)(res + idx);
                                    o.x = a0 + rr.x; o.y = a1 + rr.y; }
                else if (EP == 5) { float2 cc = *(const float2*)(C + idx);
                                    float2 mm = *(const float2*)(mul + idx);
                                    o.x = cc.x + mm.x * a0; o.y = cc.y + mm.y * a1; }
                else { // EP == 6 runtime
                    if (rt_ep == 1)      { o.x = a0 / (1.f + expf(-a0));
                                           o.y = a1 / (1.f + expf(-a1)); }
                    else if (rt_ep == 2) { float z0 = fmaxf(a0, 0.f), z1 = fmaxf(a1, 0.f);
                                           o.x = tf32r(z0 * z0); o.y = tf32r(z1 * z1); }
                    else if (rt_ep == 3) { o.x = 1.f / (1.f + expf(-a0));
                                           o.y = 1.f / (1.f + expf(-a1)); }
                    else                 { o.x = a0; o.y = a1; }
                }
                *(float2*)(C + idx) = o;
            }
        }
    }
}

template<int EP>
__global__ __launch_bounds__(256, 1) void gemm_tf32(
    const float* __restrict__ A, const float* __restrict__ B,
    float* __restrict__ C, int M, int N, int K,
    const float* __restrict__ res, const float* __restrict__ mul)
{
    extern __shared__ float smem[];
    gemm_core<EP>(A, B, C, M, N, K, res, mul, 0, smem,
                  blockIdx.y * 128, blockIdx.x * 256);
}

// 4 projection GEMMs in one launch; z==3 gets silu
__global__ __launch_bounds__(256, 1) void gemm_proj4(
    const float* __restrict__ A0, const float* __restrict__ A1,
    const float* __restrict__ A2, const float* __restrict__ A3,
    const float* __restrict__ B0, const float* __restrict__ B1,
    const float* __restrict__ B2, const float* __restrict__ B3,
    float* __restrict__ C0, float* __restrict__ C1,
    float* __restrict__ C2, float* __restrict__ C3)
{
    extern __shared__ float smem[];
    const float* A; const float* Bw; float* C;
    int z = blockIdx.z;
    if (z == 0)      { A = A0; Bw = B0; C = C0; }
    else if (z == 1) { A = A1; Bw = B1; C = C1; }
    else if (z == 2) { A = A2; Bw = B2; C = C2; }
    else             { A = A3; Bw = B3; C = C3; }
    gemm_core<6>(A, Bw, C, Mv, Cv, Cv, nullptr, nullptr, (z == 3) ? 1 : 0,
                 smem, blockIdx.y * 128, blockIdx.x * 256);
}

// FFN-K (relu^2, N=3584) + FFN-R (sigmoid, N=1024) in one launch
__global__ __launch_bounds__(256, 1) void gemm_ffnpair(
    const float* __restrict__ Ak, const float* __restrict__ Bk, float* __restrict__ Ck,
    const float* __restrict__ Ar, const float* __restrict__ Br, float* __restrict__ Cr)
{
    extern __shared__ float smem[];
    const int TK = FFNv / 256;   // 14
    if ((int)blockIdx.x < TK)
        gemm_core<6>(Ak, Bk, Ck, Mv, FFNv, Cv, nullptr, nullptr, 2,
                     smem, blockIdx.y * 128, blockIdx.x * 256);
    else
        gemm_core<6>(Ar, Br, Cr, Mv, Cv, Cv, nullptr, nullptr, 3,
                     smem, blockIdx.y * 128, (blockIdx.x - TK) * 256);
}

// ---------------------------------------------------------------------------
// WKV5 recurrence
// ---------------------------------------------------------------------------
__global__ __launch_bounds__(256) void wkv_kernel(
    const float* __restrict__ r, const float* __restrict__ k,
    const float* __restrict__ v,
    const float* __restrict__ decay, const float* __restrict__ faaaa,
    float* __restrict__ y)
{
    const int CH = 8;
    __shared__ float sr[CH][Nv], sk[CH][Nv], sv[CH][Nv];

    int bh = blockIdx.x;
    int b = bh / Hv, h = bh % Hv;
    int tid = threadIdx.x;
    int j  = tid >> 2;
    int gq = tid & 3;
    int ib = gq * 16;

    float S[16], ew[16], uu[16];
#pragma unroll
    for (int ii = 0; ii < 16; ii++) {
        S[ii]  = 0.f;
        ew[ii] = expf(-expf(decay[h * Nv + ib + ii]));
        uu[ii] = faaaa[h * Nv + ib + ii];
    }

    size_t base = ((size_t)b * Tv) * Cv + (size_t)h * Nv;

    for (int tc = 0; tc < Tv; tc += CH) {
        __syncthreads();
        for (int idx = tid; idx < CH * Nv; idx += 256) {
            int st = idx >> 6, c = idx & 63;
            size_t off = base + (size_t)(tc + st) * Cv + c;
            sr[st][c] = r[off];
            sk[st][c] = k[off];
            sv[st][c] = v[off];
        }
        __syncthreads();

#pragma unroll
        for (int st = 0; st < CH; st++) {
            float vj = sv[st][j];
            float y0 = 0.f;
#pragma unroll
            for (int ii = 0; ii < 16; ii++) {
                float ri = sr[st][ib + ii];
                float ki = sk[st][ib + ii];
                float t = ki * vj;
                y0 = fmaf(ri, fmaf(uu[ii], t, S[ii]), y0);
                S[ii] = fmaf(ew[ii], S[ii], t);
            }
            y0 += __shfl_xor_sync(0xffffffffu, y0, 1);
            y0 += __shfl_xor_sync(0xffffffffu, y0, 2);
            if (gq == 0)
                y[base + (size_t)(tc + st) * Cv + j] = y0;
        }
    }
}

// ---------------------------------------------------------------------------
// GroupNorm * gate (output tf32-rounded)
// ---------------------------------------------------------------------------
__global__ __launch_bounds__(256) void gnmul_kernel(
    const float* __restrict__ y, const float* __restrict__ g,
    const float* __restrict__ w, const float* __restrict__ b,
    float* __restrict__ ym)
{
    int m = blockIdx.x, tid = threadIdx.x;
    size_t base = (size_t)m * Cv;
    float4 v = ((const float4*)(y + base))[tid];
    const float s8 = 1.0f / 8.0f;
    v.x *= s8; v.y *= s8; v.z *= s8; v.w *= s8;

    float s  = v.x + v.y + v.z + v.w;
    float ss = v.x*v.x + v.y*v.y + v.z*v.z + v.w*v.w;
#pragma unroll
    for (int o = 8; o; o >>= 1) {
        s  += __shfl_xor_sync(0xffffffffu, s,  o);
        ss += __shfl_xor_sync(0xffffffffu, ss, o);
    }
    float mu  = s * (1.0f / Nv);
    float var = ss * (1.0f / Nv) - mu * mu;
    float inv = rsqrtf(var + EPSv);

    float4 wv = ((const float4*)w)[tid];
    float4 bv = ((const float4*)b)[tid];
    float4 gv = ((const float4*)(g + base))[tid];
    float4 o;
    o.x = tf32r(((v.x - mu) * inv * wv.x + bv.x) * gv.x);
    o.y = tf32r(((v.y - mu) * inv * wv.y + bv.y) * gv.y);
    o.z = tf32r(((v.z - mu) * inv * wv.z + bv.z) * gv.z);
    o.w = tf32r(((v.w - mu) * inv * wv.w + bv.w) * gv.w);
    ((float4*)(ym + base))[tid] = o;
}

// ---------------------------------------------------------------------------
// launch
// ---------------------------------------------------------------------------
#define GEMM_SMEM (3 * (128 * 36 + 256 * 36) * 4)   /* 165,888 B */

extern "C" void kernel_launch(void* const* d_in, const int* in_sizes, int n_in,
                              void* d_out, int out_size)
{
    const float* x        = (const float*)d_in[0];
    const float* ln0_w    = (const float*)d_in[1];
    const float* ln0_b    = (const float*)d_in[2];
    const float* ln1_w    = (const float*)d_in[3];
    const float* ln1_b    = (const float*)d_in[4];
    const float* ln2_w    = (const float*)d_in[5];
    const float* ln2_b    = (const float*)d_in[6];
    const float* att_tmk  = (const float*)d_in[7];
    const float* att_tmv  = (const float*)d_in[8];
    const float* att_tmr  = (const float*)d_in[9];
    const float* att_tmg  = (const float*)d_in[10];
    const float* att_decay  = (const float*)d_in[11];
    const float* att_faaaa  = (const float*)d_in[12];
    const float* att_Wr   = (const float*)d_in[13];
    const float* att_Wk   = (const float*)d_in[14];
    const float* att_Wv   = (const float*)d_in[15];
    const float* att_Wg   = (const float*)d_in[16];
    const float* att_Wo   = (const float*)d_in[17];
    const float* att_lnx_w = (const float*)d_in[18];
    const float* att_lnx_b = (const float*)d_in[19];
    const float* ffn_tmk  = (const float*)d_in[20];
    const float* ffn_tmr  = (const float*)d_in[21];
    const float* ffn_Wk   = (const float*)d_in[22];
    const float* ffn_Wr   = (const float*)d_in[23];
    const float* ffn_Wv   = (const float*)d_in[24];
    float* out = (float*)d_out;

    void* poolv = nullptr;
    cudaGetSymbolAddress(&poolv, g_pool);
    float* pool = (float*)poolv;

    float* bx0  = pool + OFF_X0;
    float* bxr  = pool + OFF_XR;
    float* bxk  = pool + OFF_XK;
    float* bxv  = pool + OFF_XV;
    float* bxg  = pool + OFF_XG;
    float* br   = pool + OFF_R;
    float* bk   = pool + OFF_K;
    float* bv   = pool + OFF_V;
    float* bg   = pool + OFF_G;
    float* by   = pool + OFF_Y;
    float* bym  = pool + OFF_YM;
    float* bxk2 = pool + OFF_XK2;
    float* bxr2 = pool + OFF_XR2;
    float* bsr  = pool + OFF_SR;
    float* bkf  = pool + OFF_KF;
    float* wWr  = pool + OFF_WR;
    float* wWk  = pool + OFF_WK;
    float* wWv  = pool + OFF_WV;
    float* wWg  = pool + OFF_WG;
    float* wWo  = pool + OFF_WO;
    float* wFWr = pool + OFF_FWR;
    float* wFWk = pool + OFF_FWK;
    float* wFWv = pool + OFF_FWV;

    cudaFuncSetAttribute(gemm_tf32<4>,  cudaFuncAttributeMaxDynamicSharedMemorySize, GEMM_SMEM);
    cudaFuncSetAttribute(gemm_tf32<5>,  cudaFuncAttributeMaxDynamicSharedMemorySize, GEMM_SMEM);
    cudaFuncSetAttribute(gemm_proj4,    cudaFuncAttributeMaxDynamicSharedMemorySize, GEMM_SMEM);
    cudaFuncSetAttribute(gemm_ffnpair,  cudaFuncAttributeMaxDynamicSharedMemorySize, GEMM_SMEM);

    // weight tf32 pre-round
    const int nCC4 = (int)(WCC / 4), nFC4 = (int)(WFC / 4);
    cvtw_kernel<<<(nCC4 + 255) / 256, 256>>>(att_Wr, wWr, nCC4);
    cvtw_kernel<<<(nCC4 + 255) / 256, 256>>>(att_Wk, wWk, nCC4);
    cvtw_kernel<<<(nCC4 + 255) / 256, 256>>>(att_Wv, wWv, nCC4);
    cvtw_kernel<<<(nCC4 + 255) / 256, 256>>>(att_Wg, wWg, nCC4);
    cvtw_kernel<<<(nCC4 + 255) / 256, 256>>>(att_Wo, wWo, nCC4);
    cvtw_kernel<<<(nCC4 + 255) / 256, 256>>>(ffn_Wr, wFWr, nCC4);
    cvtw_kernel<<<(nFC4 + 255) / 256, 256>>>(ffn_Wk, wFWk, nFC4);
    cvtw_kernel<<<(nFC4 + 255) / 256, 256>>>(ffn_Wv, wFWv, nFC4);

    // attention path
    ln01mix4_kernel<<<Mv, 256>>>(x, ln0_w, ln0_b, ln1_w, ln1_b,
                                 att_tmk, att_tmv, att_tmr, att_tmg,
                                 bx0, bxk, bxv, bxr, bxg);
    dim3 gP(Cv / 256, Mv / 128, 4);
    gemm_proj4<<<gP, 256, GEMM_SMEM>>>(bxr, bxk, bxv, bxg,
                                       wWr, wWk, wWv, wWg,
                                       br, bk, bv, bg);
    wkv_kernel<<<Bv * Hv, 256>>>(br, bk, bv, att_decay, att_faaaa, by);
    gnmul_kernel<<<Mv, 256>>>(by, bg, att_lnx_w, att_lnx_b, bym);
    dim3 gC(Cv / 256, Mv / 128);
    gemm_tf32<4><<<gC, 256, GEMM_SMEM>>>(bym, wWo, out, Mv, Cv, Cv, bx0, nullptr);

    // channel-mix path
    ln2mix2_kernel<<<Mv, 256>>>(out, ln2_w, ln2_b, ffn_tmk, ffn_tmr, bxk2, bxr2);
    dim3 gPair(FFNv / 256 + Cv / 256, Mv / 128);    // (18,128)
    gemm_ffnpair<<<gPair, 256, GEMM_SMEM>>>(bxk2, wFWk, bkf, bxr2, wFWr, bsr);
    gemm_tf32<5><<<gC, 256, GEMM_SMEM>>>(bkf, wFWv, out, Mv, Cv, FFNv, nullptr, bsr);
}

// round 8
// speedup vs baseline: 4.3798x; 1.4710x over previous
#include <cuda_runtime.h>
#include <cuda_fp16.h>
#include <cstdint>
#include <math.h>

#define Bv   8
#define Tv   2048
#define Cv   1024
#define Hv   16
#define Nv   64
#define FFNv 3584
#define Mv   (Bv*Tv)          /* 16384 tokens */
#define EPSv 1e-5f

// ---------------------------------------------------------------------------
// Scratch pool (static device memory; no allocations anywhere).
// Half buffers reuse float-sized slots (waste ok, alignment guaranteed).
// ---------------------------------------------------------------------------
#define MC   ((size_t)Mv * Cv)        /* 16,777,216 */
#define MF   ((size_t)Mv * FFNv)      /* 58,720,256 */
#define WCC  ((size_t)Cv * Cv)        /* 1,048,576  */
#define WFC  ((size_t)FFNv * Cv)      /* 3,670,016  */
__device__ float g_pool[16 * MC + MF + 6 * WCC + 2 * WFC];

#define OFF_X0   (0*MC)
#define OFF_XR   (2*MC)
#define OFF_XK   (3*MC)
#define OFF_XV   (4*MC)
#define OFF_XG   (5*MC)
#define OFF_R    (6*MC)
#define OFF_K    (7*MC)
#define OFF_V    (8*MC)
#define OFF_G    (9*MC)
#define OFF_Y    (10*MC)
#define OFF_YM   (11*MC)
#define OFF_XK2  (13*MC)
#define OFF_XR2  (14*MC)
#define OFF_SR   (15*MC)
#define OFF_KF   (16*MC)
#define OFF_W    (16*MC + MF)
#define OFF_WR   (OFF_W + 0*WCC)
#define OFF_WK   (OFF_W + 1*WCC)
#define OFF_WV   (OFF_W + 2*WCC)
#define OFF_WG   (OFF_W + 3*WCC)
#define OFF_WO   (OFF_W + 4*WCC)
#define OFF_FWR  (OFF_W + 5*WCC)
#define OFF_FWK  (OFF_W + 6*WCC)
#define OFF_FWV  (OFF_W + 6*WCC + WFC)

// ---------------------------------------------------------------------------
// helpers
// ---------------------------------------------------------------------------
__device__ __forceinline__ float4 block_reduce4(float a, float b, float c, float d,
                                                float* shm /*32*/)
{
#pragma unroll
    for (int o = 16; o; o >>= 1) {
        a += __shfl_xor_sync(0xffffffffu, a, o);
        b += __shfl_xor_sync(0xffffffffu, b, o);
        c += __shfl_xor_sync(0xffffffffu, c, o);
        d += __shfl_xor_sync(0xffffffffu, d, o);
    }
    int w = threadIdx.x >> 5;
    if ((threadIdx.x & 31) == 0) { shm[w] = a; shm[8+w] = b; shm[16+w] = c; shm[24+w] = d; }
    __syncthreads();
    a = shm[0]; b = shm[8]; c = shm[16]; d = shm[24];
#pragma unroll
    for (int i = 1; i < 8; i++) {
        a += shm[i]; b += shm[8+i]; c += shm[16+i]; d += shm[24+i];
    }
    return make_float4(a, b, c, d);
}

__device__ __forceinline__ void st_half4(__half* p, size_t i4, float4 v)
{
    __half2 lo = __floats2half2_rn(v.x, v.y);
    __half2 hi = __floats2half2_rn(v.z, v.w);
    uint2 u;
    u.x = *reinterpret_cast<unsigned*>(&lo);
    u.y = *reinterpret_cast<unsigned*>(&hi);
    *reinterpret_cast<uint2*>(p + i4 * 4) = u;
}

__device__ __forceinline__ void cp_async16(void* smem, const void* gptr)
{
    unsigned saddr = (unsigned)__cvta_generic_to_shared(smem);
    asm volatile("cp.async.ca.shared.global [%0], [%1], 16;\n" :: "r"(saddr), "l"(gptr));
}
#define CP_COMMIT() asm volatile("cp.async.commit_group;\n" ::: "memory")
#define CP_WAIT0()  asm volatile("cp.async.wait_group 0;\n" ::: "memory")
#define CP_WAIT1()  asm volatile("cp.async.wait_group 1;\n" ::: "memory")

#define LDSM4(r0, r1, r2, r3, addr) \
    asm volatile("ldmatrix.sync.aligned.m8n8.x4.shared.b16 {%0,%1,%2,%3}, [%4];" \
                 : "=r"(r0), "=r"(r1), "=r"(r2), "=r"(r3) : "r"(addr))

// ---------------------------------------------------------------------------
// weight fp32 -> fp16
// ---------------------------------------------------------------------------
__global__ __launch_bounds__(256) void cvtw_kernel(
    const float* __restrict__ in, __half* __restrict__ outp, int n4)
{
    int idx = blockIdx.x * blockDim.x + threadIdx.x;
    if (idx >= n4) return;
    float4 v = ((const float4*)in)[idx];
    st_half4(outp, idx, v);
}

// ---------------------------------------------------------------------------
// Fused LN0+LN1+token-shift-mix4 (attention front) -> half outputs
// ---------------------------------------------------------------------------
__global__ __launch_bounds__(256) void ln01mix4_kernel(
    const float* __restrict__ x,
    const float* __restrict__ w0, const float* __restrict__ b0,
    const float* __restrict__ w1, const float* __restrict__ b1,
    const float* __restrict__ tmk, const float* __restrict__ tmv,
    const float* __restrict__ tmr, const float* __restrict__ tmg,
    float* __restrict__ x0,
    __half* __restrict__ xk, __half* __restrict__ xv,
    __half* __restrict__ xr, __half* __restrict__ xg)
{
    __shared__ float shm1[32], shm2[32];
    int m = blockIdx.x, tid = threadIdx.x;
    bool hp = (m % Tv) != 0;

    const float4 vc = ((const float4*)(x + (size_t)m * Cv))[tid];
    float4 vp = make_float4(0.f, 0.f, 0.f, 0.f);
    if (hp) vp = ((const float4*)(x + (size_t)(m - 1) * Cv))[tid];

    float4 r0 = block_reduce4(
        vc.x + vc.y + vc.z + vc.w,
        vc.x*vc.x + vc.y*vc.y + vc.z*vc.z + vc.w*vc.w,
        vp.x + vp.y + vp.z + vp.w,
        vp.x*vp.x + vp.y*vp.y + vp.z*vp.z + vp.w*vp.w, shm1);

    float muc = r0.x * (1.0f / Cv);
    float ivc = rsqrtf(r0.y * (1.0f / Cv) - muc * muc + EPSv);
    float mup = r0.z * (1.0f / Cv);
    float ivp = rsqrtf(r0.w * (1.0f / Cv) - mup * mup + EPSv);

    const float4 w0v = ((const float4*)w0)[tid];
    const float4 b0v = ((const float4*)b0)[tid];
    float4 c0, p0;
    c0.x = (vc.x - muc) * ivc * w0v.x + b0v.x;
    c0.y = (vc.y - muc) * ivc * w0v.y + b0v.y;
    c0.z = (vc.z - muc) * ivc * w0v.z + b0v.z;
    c0.w = (vc.w - muc) * ivc * w0v.w + b0v.w;
    p0.x = (vp.x - mup) * ivp * w0v.x + b0v.x;
    p0.y = (vp.y - mup) * ivp * w0v.y + b0v.y;
    p0.z = (vp.z - mup) * ivp * w0v.z + b0v.z;
    p0.w = (vp.w - mup) * ivp * w0v.w + b0v.w;
    ((float4*)(x0 + (size_t)m * Cv))[tid] = c0;

    float4 r1 = block_reduce4(
        c0.x + c0.y + c0.z + c0.w,
        c0.x*c0.x + c0.y*c0.y + c0.z*c0.z + c0.w*c0.w,
        p0.x + p0.y + p0.z + p0.w,
        p0.x*p0.x + p0.y*p0.y + p0.z*p0.z + p0.w*p0.w, shm2);

    muc = r1.x * (1.0f / Cv);
    ivc = rsqrtf(r1.y * (1.0f / Cv) - muc * muc + EPSv);
    mup = r1.z * (1.0f / Cv);
    ivp = rsqrtf(r1.w * (1.0f / Cv) - mup * mup + EPSv);

    const float4 w1v = ((const float4*)w1)[tid];
    const float4 b1v = ((const float4*)b1)[tid];
    float4 xnc, xnp;
    xnc.x = (c0.x - muc) * ivc * w1v.x + b1v.x;
    xnc.y = (c0.y - muc) * ivc * w1v.y + b1v.y;
    xnc.z = (c0.z - muc) * ivc * w1v.z + b1v.z;
    xnc.w = (c0.w - muc) * ivc * w1v.w + b1v.w;
    if (hp) {
        xnp.x = (p0.x - mup) * ivp * w1v.x + b1v.x;
        xnp.y = (p0.y - mup) * ivp * w1v.y + b1v.y;
        xnp.z = (p0.z - mup) * ivp * w1v.z + b1v.z;
        xnp.w = (p0.w - mup) * ivp * w1v.w + b1v.w;
    } else {
        xnp = make_float4(0.f, 0.f, 0.f, 0.f);
    }
    float4 dd = make_float4(xnc.x - xnp.x, xnc.y - xnp.y,
                            xnc.z - xnp.z, xnc.w - xnp.w);
    size_t idx = (size_t)m * (Cv / 4) + tid;

#define DO_MIX(TM, OUT) { \
    float4 w = ((const float4*)TM)[tid]; \
    float4 o; \
    o.x = fmaf(dd.x, w.x, xnp.x); o.y = fmaf(dd.y, w.y, xnp.y); \
    o.z = fmaf(dd.z, w.z, xnp.z); o.w = fmaf(dd.w, w.w, xnp.w); \
    st_half4(OUT, idx, o); }

    DO_MIX(tmk, xk)
    DO_MIX(tmv, xv)
    DO_MIX(tmr, xr)
    DO_MIX(tmg, xg)
#undef DO_MIX
}

// ---------------------------------------------------------------------------
// Fused LN2+token-shift-mix2 (channel-mix front) -> half outputs
// ---------------------------------------------------------------------------
__global__ __launch_bounds__(256) void ln2mix2_kernel(
    const float* __restrict__ in,
    const float* __restrict__ w2, const float* __restrict__ b2,
    const float* __restrict__ tmk, const float* __restrict__ tmr,
    __half* __restrict__ xk, __half* __restrict__ xr)
{
    __shared__ float shm[32];
    int m = blockIdx.x, tid = threadIdx.x;
    bool hp = (m % Tv) != 0;

    const float4 vc = ((const float4*)(in + (size_t)m * Cv))[tid];
    float4 vp = make_float4(0.f, 0.f, 0.f, 0.f);
    if (hp) vp = ((const float4*)(in + (size_t)(m - 1) * Cv))[tid];

    float4 r0 = block_reduce4(
        vc.x + vc.y + vc.z + vc.w,
        vc.x*vc.x + vc.y*vc.y + vc.z*vc.z + vc.w*vc.w,
        vp.x + vp.y + vp.z + vp.w,
        vp.x*vp.x + vp.y*vp.y + vp.z*vp.z + vp.w*vp.w, shm);

    float muc = r0.x * (1.0f / Cv);
    float ivc = rsqrtf(r0.y * (1.0f / Cv) - muc * muc + EPSv);
    float mup = r0.z * (1.0f / Cv);
    float ivp = rsqrtf(r0.w * (1.0f / Cv) - mup * mup + EPSv);

    const float4 wv = ((const float4*)w2)[tid];
    const float4 bv = ((const float4*)b2)[tid];
    float4 xnc, xnp;
    xnc.x = (vc.x - muc) * ivc * wv.x + bv.x;
    xnc.y = (vc.y - muc) * ivc * wv.y + bv.y;
    xnc.z = (vc.z - muc) * ivc * wv.z + bv.z;
    xnc.w = (vc.w - muc) * ivc * wv.w + bv.w;
    if (hp) {
        xnp.x = (vp.x - mup) * ivp * wv.x + bv.x;
        xnp.y = (vp.y - mup) * ivp * wv.y + bv.y;
        xnp.z = (vp.z - mup) * ivp * wv.z + bv.z;
        xnp.w = (vp.w - mup) * ivp * wv.w + bv.w;
    } else {
        xnp = make_float4(0.f, 0.f, 0.f, 0.f);
    }
    float4 dd = make_float4(xnc.x - xnp.x, xnc.y - xnp.y,
                            xnc.z - xnp.z, xnc.w - xnp.w);
    size_t idx = (size_t)m * (Cv / 4) + tid;

#define DO_MIX(TM, OUT) { \
    float4 w = ((const float4*)TM)[tid]; \
    float4 o; \
    o.x = fmaf(dd.x, w.x, xnp.x); o.y = fmaf(dd.y, w.y, xnp.y); \
    o.z = fmaf(dd.z, w.z, xnp.z); o.w = fmaf(dd.w, w.w, xnp.w); \
    st_half4(OUT, idx, o); }

    DO_MIX(tmk, xk)
    DO_MIX(tmr, xr)
#undef DO_MIX
}

// ---------------------------------------------------------------------------
// FP16 tensor-core NT GEMM core: C[M,N] = A[M,K] @ B[N,K]^T, fp32 accum.
// CTA tile 128x256x64, 8 warps of 64x64, 3-stage cp.async, pitch P=72 halves.
// EP: 4 +res(f32), 5 C(f32) += mul*acc, 6 runtime {0 none,1 silu,
//     2 relu^2 -> HALF out, 3 sigmoid}
// ---------------------------------------------------------------------------
template<int EP>
__device__ __forceinline__ void gemm_core(
    const __half* __restrict__ A, const __half* __restrict__ B,
    void* __restrict__ Cp, int M, int N, int K,
    const float* __restrict__ res, const float* __restrict__ mul,
    int rt_ep, __half* smem, int bm, int bn)
{
    const int BM = 128, BN = 256, BK = 64, P = 72;
    __half* As = smem;                      // [3][128][72]
    __half* Bs = smem + 3 * BM * P;         // [3][256][72]

    const int tid  = threadIdx.x;
    const int wid  = tid >> 5;
    const int lane = tid & 31;
    const int warp_m = (wid & 1) * 64;
    const int warp_n = (wid >> 1) * 64;
    const int gr = lane >> 2;
    const int gc = lane & 3;

    const __half* Abase = A + (size_t)bm * K;
    const __half* Bbase = B + (size_t)bn * K;

    const unsigned asmem = (unsigned)__cvta_generic_to_shared(As);
    const unsigned bsmem = (unsigned)__cvta_generic_to_shared(Bs);
    // A frag: row = warp_m + (lane&15), col halves = (lane&16)>>1
    const unsigned aoff = asmem + (unsigned)(((warp_m + (lane & 15)) * P + ((lane & 16) >> 1)) * 2);
    // B frag: row = warp_n + (lane&7) + ((lane&16)>>1), col halves = (lane&8)
    const unsigned boff = bsmem + (unsigned)(((warp_n + (lane & 7) + ((lane & 16) >> 1)) * P + (lane & 8)) * 2);
    const unsigned BUFA = BM * P * 2;
    const unsigned BUFB = BN * P * 2;
    const unsigned R16  = 16 * P * 2;

    const int arow = tid >> 3;      // 0..31
    const int aseg = tid & 7;       // 16B segments (8 halves)

#define PREFETCH(kt, buf) { \
    int k0 = (kt) * BK; \
    _Pragma("unroll") \
    for (int c = 0; c < 4; c++) { \
        int row = arow + c * 32; \
        cp_async16(As + (buf) * BM * P + row * P + aseg * 8, \
                   Abase + (size_t)row * K + k0 + aseg * 8); \
    } \
    _Pragma("unroll") \
    for (int c = 0; c < 8; c++) { \
        int row = arow + c * 32; \
        cp_async16(Bs + (buf) * BN * P + row * P + aseg * 8, \
                   Bbase + (size_t)row * K + k0 + aseg * 8); \
    } \
    CP_COMMIT(); }

    float acc[4][8][4];
#pragma unroll
    for (int mt = 0; mt < 4; mt++)
#pragma unroll
        for (int nt = 0; nt < 8; nt++)
#pragma unroll
            for (int q = 0; q < 4; q++) acc[mt][nt][q] = 0.f;

    const int NT = K / BK;
    PREFETCH(0, 0)
    PREFETCH(1, 1)

    int buf = 0;
    for (int kt = 0; kt < NT; kt++) {
        if (kt + 1 < NT) { CP_WAIT1(); } else { CP_WAIT0(); }
        __syncthreads();
        int nbuf = buf + 2; if (nbuf >= 3) nbuf -= 3;
        if (kt + 2 < NT) PREFETCH(kt + 2, nbuf)

        const unsigned ab = aoff + buf * BUFA;
        const unsigned bb = boff + buf * BUFB;
#pragma unroll
        for (int kk = 0; kk < BK; kk += 16) {
            uint32_t af[4][4], bf[8][2];
#pragma unroll
            for (int mt = 0; mt < 4; mt++)
                LDSM4(af[mt][0], af[mt][1], af[mt][2], af[mt][3],
                      ab + mt * R16 + kk * 2);
#pragma unroll
            for (int p = 0; p < 4; p++)
                LDSM4(bf[2*p][0], bf[2*p][1], bf[2*p+1][0], bf[2*p+1][1],
                      bb + p * R16 + kk * 2);
#pragma unroll
            for (int mt = 0; mt < 4; mt++)
#pragma unroll
                for (int nt = 0; nt < 8; nt++) {
                    asm volatile(
                        "mma.sync.aligned.m16n8k16.row.col.f32.f16.f16.f32 "
                        "{%0,%1,%2,%3}, {%4,%5,%6,%7}, {%8,%9}, {%0,%1,%2,%3};"
                        : "+f"(acc[mt][nt][0]), "+f"(acc[mt][nt][1]),
                          "+f"(acc[mt][nt][2]), "+f"(acc[mt][nt][3])
                        : "r"(af[mt][0]), "r"(af[mt][1]), "r"(af[mt][2]), "r"(af[mt][3]),
                          "r"(bf[nt][0]), "r"(bf[nt][1]));
                }
        }
        buf = buf + 1; if (buf >= 3) buf -= 3;
    }
#undef PREFETCH

    float* Cf = (float*)Cp;
    __half* Ch = (__half*)Cp;
#pragma unroll
    for (int mt = 0; mt < 4; mt++) {
#pragma unroll
        for (int nt = 0; nt < 8; nt++) {
            int row = bm + warp_m + mt * 16 + gr;
            int col = bn + warp_n + nt * 8 + 2 * gc;
#pragma unroll
            for (int half_ = 0; half_ < 2; half_++) {
                size_t idx = (size_t)(row + half_ * 8) * N + col;
                float a0 = acc[mt][nt][half_ * 2 + 0];
                float a1 = acc[mt][nt][half_ * 2 + 1];
                if (EP == 4) {
                    float2 rr = *(const float2*)(res + idx);
                    *(float2*)(Cf + idx) = make_float2(a0 + rr.x, a1 + rr.y);
                } else if (EP == 5) {
                    float2 cc = *(const float2*)(Cf + idx);
                    float2 mm = *(const float2*)(mul + idx);
                    *(float2*)(Cf + idx) = make_float2(cc.x + mm.x * a0,
                                                       cc.y + mm.y * a1);
                } else { // EP == 6 runtime
                    if (rt_ep == 2) {       // relu^2 -> half
                        float z0 = fmaxf(a0, 0.f), z1 = fmaxf(a1, 0.f);
                        __half2 h = __floats2half2_rn(z0 * z0, z1 * z1);
                        *(__half2*)(Ch + idx) = h;
                    } else {
                        float2 o;
                        if (rt_ep == 1)      { o.x = a0 / (1.f + expf(-a0));
                                               o.y = a1 / (1.f + expf(-a1)); }
                        else if (rt_ep == 3) { o.x = 1.f / (1.f + expf(-a0));
                                               o.y = 1.f / (1.f + expf(-a1)); }
                        else                 { o.x = a0; o.y = a1; }
                        *(float2*)(Cf + idx) = o;
                    }
                }
            }
        }
    }
}

template<int EP>
__global__ __launch_bounds__(256, 1) void gemm_f16(
    const __half* __restrict__ A, const __half* __restrict__ B,
    void* __restrict__ C, int M, int N, int K,
    const float* __restrict__ res, const float* __restrict__ mul)
{
    extern __shared__ __half smem[];
    gemm_core<EP>(A, B, C, M, N, K, res, mul, 0, smem,
                  blockIdx.y * 128, blockIdx.x * 256);
}

// 4 projection GEMMs in one launch; z==3 gets silu. Outputs fp32.
__global__ __launch_bounds__(256, 1) void gemm_proj4(
    const __half* __restrict__ A0, const __half* __restrict__ A1,
    const __half* __restrict__ A2, const __half* __restrict__ A3,
    const __half* __restrict__ B0, const __half* __restrict__ B1,
    const __half* __restrict__ B2, const __half* __restrict__ B3,
    float* __restrict__ C0, float* __restrict__ C1,
    float* __restrict__ C2, float* __restrict__ C3)
{
    extern __shared__ __half smem[];
    const __half* A; const __half* Bw; float* C;
    int z = blockIdx.z;
    if (z == 0)      { A = A0; Bw = B0; C = C0; }
    else if (z == 1) { A = A1; Bw = B1; C = C1; }
    else if (z == 2) { A = A2; Bw = B2; C = C2; }
    else             { A = A3; Bw = B3; C = C3; }
    gemm_core<6>(A, Bw, C, Mv, Cv, Cv, nullptr, nullptr, (z == 3) ? 1 : 0,
                 smem, blockIdx.y * 128, blockIdx.x * 256);
}

// FFN-K (relu^2 -> half, N=3584) + FFN-R (sigmoid -> f32, N=1024) in one launch
__global__ __launch_bounds__(256, 1) void gemm_ffnpair(
    const __half* __restrict__ Ak, const __half* __restrict__ Bk, __half* __restrict__ Ck,
    const __half* __restrict__ Ar, const __half* __restrict__ Br, float* __restrict__ Cr)
{
    extern __shared__ __half smem[];
    const int TK = FFNv / 256;   // 14
    if ((int)blockIdx.x < TK)
        gemm_core<6>(Ak, Bk, Ck, Mv, FFNv, Cv, nullptr, nullptr, 2,
                     smem, blockIdx.y * 128, blockIdx.x * 256);
    else
        gemm_core<6>(Ar, Br, Cr, Mv, Cv, Cv, nullptr, nullptr, 3,
                     smem, blockIdx.y * 128, (blockIdx.x - TK) * 256);
}

// ---------------------------------------------------------------------------
// WKV5 recurrence (fp32)
// ---------------------------------------------------------------------------
__global__ __launch_bounds__(256) void wkv_kernel(
    const float* __restrict__ r, const float* __restrict__ k,
    const float* __restrict__ v,
    const float* __restrict__ decay, const float* __restrict__ faaaa,
    float* __restrict__ y)
{
    const int CH = 8;
    __shared__ float sr[CH][Nv], sk[CH][Nv], sv[CH][Nv];

    int bh = blockIdx.x;
    int b = bh / Hv, h = bh % Hv;
    int tid = threadIdx.x;
    int j  = tid >> 2;
    int gq = tid & 3;
    int ib = gq * 16;

    float S[16], ew[16], uu[16];
#pragma unroll
    for (int ii = 0; ii < 16; ii++) {
        S[ii]  = 0.f;
        ew[ii] = expf(-expf(decay[h * Nv + ib + ii]));
        uu[ii] = faaaa[h * Nv + ib + ii];
    }

    size_t base = ((size_t)b * Tv) * Cv + (size_t)h * Nv;

    for (int tc = 0; tc < Tv; tc += CH) {
        __syncthreads();
        for (int idx = tid; idx < CH * Nv; idx += 256) {
            int st = idx >> 6, c = idx & 63;
            size_t off = base + (size_t)(tc + st) * Cv + c;
            sr[st][c] = r[off];
            sk[st][c] = k[off];
            sv[st][c] = v[off];
        }
        __syncthreads();

#pragma unroll
        for (int st = 0; st < CH; st++) {
            float vj = sv[st][j];
            float y0 = 0.f;
#pragma unroll
            for (int ii = 0; ii < 16; ii++) {
                float ri = sr[st][ib + ii];
                float ki = sk[st][ib + ii];
                float t = ki * vj;
                y0 = fmaf(ri, fmaf(uu[ii], t, S[ii]), y0);
                S[ii] = fmaf(ew[ii], S[ii], t);
            }
            y0 += __shfl_xor_sync(0xffffffffu, y0, 1);
            y0 += __shfl_xor_sync(0xffffffffu, y0, 2);
            if (gq == 0)
                y[base + (size_t)(tc + st) * Cv + j] = y0;
        }
    }
}

// ---------------------------------------------------------------------------
// GroupNorm * gate -> half output (feeds Wo GEMM)
// ---------------------------------------------------------------------------
__global__ __launch_bounds__(256) void gnmul_kernel(
    const float* __restrict__ y, const float* __restrict__ g,
    const float* __restrict__ w, const float* __restrict__ b,
    __half* __restrict__ ym)
{
    int m = blockIdx.x, tid = threadIdx.x;
    size_t base = (size_t)m * Cv;
    float4 v = ((const float4*)(y + base))[tid];
    const float s8 = 1.0f / 8.0f;
    v.x *= s8; v.y *= s8; v.z *= s8; v.w *= s8;

    float s  = v.x + v.y + v.z + v.w;
    float ss = v.x*v.x + v.y*v.y + v.z*v.z + v.w*v.w;
#pragma unroll
    for (int o = 8; o; o >>= 1) {
        s  += __shfl_xor_sync(0xffffffffu, s,  o);
        ss += __shfl_xor_sync(0xffffffffu, ss, o);
    }
    float mu  = s * (1.0f / Nv);
    float var = ss * (1.0f / Nv) - mu * mu;
    float inv = rsqrtf(var + EPSv);

    float4 wv = ((const float4*)w)[tid];
    float4 bv = ((const float4*)b)[tid];
    float4 gv = ((const float4*)(g + base))[tid];
    float4 o;
    o.x = ((v.x - mu) * inv * wv.x + bv.x) * gv.x;
    o.y = ((v.y - mu) * inv * wv.y + bv.y) * gv.y;
    o.z = ((v.z - mu) * inv * wv.z + bv.z) * gv.z;
    o.w = ((v.w - mu) * inv * wv.w + bv.w) * gv.w;
    st_half4(ym, base / 4 + tid, o);
}

// ---------------------------------------------------------------------------
// launch
// ---------------------------------------------------------------------------
#define GEMM_SMEM (3 * (128 * 72 + 256 * 72) * 2)   /* 165,888 B */

extern "C" void kernel_launch(void* const* d_in, const int* in_sizes, int n_in,
                              void* d_out, int out_size)
{
    const float* x        = (const float*)d_in[0];
    const float* ln0_w    = (const float*)d_in[1];
    const float* ln0_b    = (const float*)d_in[2];
    const float* ln1_w    = (const float*)d_in[3];
    const float* ln1_b    = (const float*)d_in[4];
    const float* ln2_w    = (const float*)d_in[5];
    const float* ln2_b    = (const float*)d_in[6];
    const float* att_tmk  = (const float*)d_in[7];
    const float* att_tmv  = (const float*)d_in[8];
    const float* att_tmr  = (const float*)d_in[9];
    const float* att_tmg  = (const float*)d_in[10];
    const float* att_decay  = (const float*)d_in[11];
    const float* att_faaaa  = (const float*)d_in[12];
    const float* att_Wr   = (const float*)d_in[13];
    const float* att_Wk   = (const float*)d_in[14];
    const float* att_Wv   = (const float*)d_in[15];
    const float* att_Wg   = (const float*)d_in[16];
    const float* att_Wo   = (const float*)d_in[17];
    const float* att_lnx_w = (const float*)d_in[18];
    const float* att_lnx_b = (const float*)d_in[19];
    const float* ffn_tmk  = (const float*)d_in[20];
    const float* ffn_tmr  = (const float*)d_in[21];
    const float* ffn_Wk   = (const float*)d_in[22];
    const float* ffn_Wr   = (const float*)d_in[23];
    const float* ffn_Wv   = (const float*)d_in[24];
    float* out = (float*)d_out;

    void* poolv = nullptr;
    cudaGetSymbolAddress(&poolv, g_pool);
    float* pool = (float*)poolv;

    float*  bx0  = pool + OFF_X0;
    __half* bxr  = (__half*)(pool + OFF_XR);
    __half* bxk  = (__half*)(pool + OFF_XK);
    __half* bxv  = (__half*)(pool + OFF_XV);
    __half* bxg  = (__half*)(pool + OFF_XG);
    float*  br   = pool + OFF_R;
    float*  bk   = pool + OFF_K;
    float*  bv   = pool + OFF_V;
    float*  bg   = pool + OFF_G;
    float*  by   = pool + OFF_Y;
    __half* bym  = (__half*)(pool + OFF_YM);
    __half* bxk2 = (__half*)(pool + OFF_XK2);
    __half* bxr2 = (__half*)(pool + OFF_XR2);
    float*  bsr  = pool + OFF_SR;
    __half* bkf  = (__half*)(pool + OFF_KF);
    __half* wWr  = (__half*)(pool + OFF_WR);
    __half* wWk  = (__half*)(pool + OFF_WK);
    __half* wWv  = (__half*)(pool + OFF_WV);
    __half* wWg  = (__half*)(pool + OFF_WG);
    __half* wWo  = (__half*)(pool + OFF_WO);
    __half* wFWr = (__half*)(pool + OFF_FWR);
    __half* wFWk = (__half*)(pool + OFF_FWK);
    __half* wFWv = (__half*)(pool + OFF_FWV);

    cudaFuncSetAttribute(gemm_f16<4>,  cudaFuncAttributeMaxDynamicSharedMemorySize, GEMM_SMEM);
    cudaFuncSetAttribute(gemm_f16<5>,  cudaFuncAttributeMaxDynamicSharedMemorySize, GEMM_SMEM);
    cudaFuncSetAttribute(gemm_proj4,   cudaFuncAttributeMaxDynamicSharedMemorySize, GEMM_SMEM);
    cudaFuncSetAttribute(gemm_ffnpair, cudaFuncAttributeMaxDynamicSharedMemorySize, GEMM_SMEM);

    // weight fp16 pre-convert
    const int nCC4 = (int)(WCC / 4), nFC4 = (int)(WFC / 4);
    cvtw_kernel<<<(nCC4 + 255) / 256, 256>>>(att_Wr, wWr, nCC4);
    cvtw_kernel<<<(nCC4 + 255) / 256, 256>>>(att_Wk, wWk, nCC4);
    cvtw_kernel<<<(nCC4 + 255) / 256, 256>>>(att_Wv, wWv, nCC4);
    cvtw_kernel<<<(nCC4 + 255) / 256, 256>>>(att_Wg, wWg, nCC4);
    cvtw_kernel<<<(nCC4 + 255) / 256, 256>>>(att_Wo, wWo, nCC4);
    cvtw_kernel<<<(nCC4 + 255) / 256, 256>>>(ffn_Wr, wFWr, nCC4);
    cvtw_kernel<<<(nFC4 + 255) / 256, 256>>>(ffn_Wk, wFWk, nFC4);
    cvtw_kernel<<<(nFC4 + 255) / 256, 256>>>(ffn_Wv, wFWv, nFC4);

    // attention path
    ln01mix4_kernel<<<Mv, 256>>>(x, ln0_w, ln0_b, ln1_w, ln1_b,
                                 att_tmk, att_tmv, att_tmr, att_tmg,
                                 bx0, bxk, bxv, bxr, bxg);
    dim3 gP(Cv / 256, Mv / 128, 4);
    gemm_proj4<<<gP, 256, GEMM_SMEM>>>(bxr, bxk, bxv, bxg,
                                       wWr, wWk, wWv, wWg,
                                       br, bk, bv, bg);
    wkv_kernel<<<Bv * Hv, 256>>>(br, bk, bv, att_decay, att_faaaa, by);
    gnmul_kernel<<<Mv, 256>>>(by, bg, att_lnx_w, att_lnx_b, bym);
    dim3 gC(Cv / 256, Mv / 128);
    gemm_f16<4><<<gC, 256, GEMM_SMEM>>>(bym, wWo, out, Mv, Cv, Cv, bx0, nullptr);

    // channel-mix path
    ln2mix2_kernel<<<Mv, 256>>>(out, ln2_w, ln2_b, ffn_tmk, ffn_tmr, bxk2, bxr2);
    dim3 gPair(FFNv / 256 + Cv / 256, Mv / 128);    // (18,128)
    gemm_ffnpair<<<gPair, 256, GEMM_SMEM>>>(bxk2, wFWk, bkf, bxr2, wFWr, bsr);
    gemm_f16<5><<<gC, 256, GEMM_SMEM>>>(bkf, wFWv, out, Mv, Cv, FFNv, nullptr, bsr);
}